// round 1
// baseline (speedup 1.0000x reference)
#include <cuda_runtime.h>
#include <cuda_bf16.h>
#include <math.h>

// Problem constants (fixed dataset: N_way=16, K_shot=32, Q=65536, D=1024)
constexpr int NS = 512;   // support samples
constexpr int D  = 1024;  // feature dim
constexpr int NW = 16;    // classes

// Fused-kernel tiling
constexpr int BM = 128;   // queries per block
constexpr int BN = 64;    // support per s-tile
constexpr int BK = 32;    // k-tile
constexpr int AS_STRIDE = BM + 4;  // 132
constexpr int BS_STRIDE = BN + 4;  // 68

// Scratch (device globals; no allocations allowed)
__device__ float g_Kss[NS * NS];
__device__ float g_LT[NS * NS];
__device__ float g_alpha[NS * NW];
__device__ float g_sqs[NS];

// ---------------------------------------------------------------------------
// 1) squared norms of support rows
// ---------------------------------------------------------------------------
__global__ void sqs_kernel(const float* __restrict__ Zs) {
    int i = blockIdx.x;
    int tid = threadIdx.x;                  // 256 threads
    const float4* z = (const float4*)(Zs + (size_t)i * D);
    float s = 0.f;
    for (int t = tid; t < D / 4; t += 256) {
        float4 v = z[t];
        s += v.x * v.x + v.y * v.y + v.z * v.z + v.w * v.w;
    }
    #pragma unroll
    for (int d = 16; d; d >>= 1) s += __shfl_xor_sync(0xffffffffu, s, d);
    __shared__ float r[8];
    if ((tid & 31) == 0) r[tid >> 5] = s;
    __syncthreads();
    if (tid == 0) {
        float t = 0.f;
        #pragma unroll
        for (int j = 0; j < 8; ++j) t += r[j];
        g_sqs[i] = t;
    }
}

// ---------------------------------------------------------------------------
// 2) Kss = rbf(Zs,Zs) + noise*I
// ---------------------------------------------------------------------------
__global__ void kss_kernel(const float* __restrict__ Zs,
                           const float* __restrict__ log_ls_p,
                           const float* __restrict__ log_noise_p) {
    __shared__ float a[16][17], b[16][17];
    int tx = threadIdx.x, ty = threadIdx.y;
    int row = blockIdx.y * 16 + ty;
    int col = blockIdx.x * 16 + tx;
    float acc = 0.f;
    for (int kt = 0; kt < D; kt += 16) {
        a[ty][tx] = Zs[(size_t)row * D + kt + tx];
        b[ty][tx] = Zs[(size_t)(blockIdx.x * 16 + ty) * D + kt + tx];
        __syncthreads();
        #pragma unroll
        for (int k = 0; k < 16; ++k) acc += a[ty][k] * b[tx][k];
        __syncthreads();
    }
    float inv2  = 0.5f * __expf(-2.0f * (*log_ls_p));
    float noise = __expf(2.0f * (*log_noise_p));
    float d2 = fmaxf(g_sqs[row] + g_sqs[col] - 2.0f * acc, 0.0f);
    float v = __expf(-d2 * inv2) + (row == col ? noise : 0.0f);
    g_Kss[row * NS + col] = v;
}

// ---------------------------------------------------------------------------
// 3) Blocked Cholesky: panel (in smem) + trailing SYRK
// ---------------------------------------------------------------------------
__global__ void chol_panel_kernel(int p) {
    extern __shared__ float P[];            // [rows][65]
    const int j0 = p * 64;
    const int rows = NS - j0;
    const int tid = threadIdx.x;            // 1024 threads
    for (int e = tid; e < rows * 64; e += 1024) {
        int r = e >> 6, c = e & 63;
        P[r * 65 + c] = g_Kss[(size_t)(j0 + r) * NS + j0 + c];
    }
    __syncthreads();
    __shared__ float sinv;
    for (int jl = 0; jl < 64; ++jl) {
        if (tid == 0) {
            float s = sqrtf(P[jl * 65 + jl]);
            P[jl * 65 + jl] = s;
            sinv = 1.0f / s;
        }
        __syncthreads();
        for (int i = jl + 1 + tid; i < rows; i += 1024) P[i * 65 + jl] *= sinv;
        __syncthreads();
        if (jl < 63) {
            int c = jl + 1 + (tid & 63);
            for (int i = jl + 1 + (tid >> 6); i < rows; i += 16) {
                if (c < 64) P[i * 65 + c] -= P[i * 65 + jl] * P[c * 65 + jl];
            }
        }
        __syncthreads();
    }
    for (int e = tid; e < rows * 64; e += 1024) {
        int r = e >> 6, c = e & 63;
        g_Kss[(size_t)(j0 + r) * NS + j0 + c] = P[r * 65 + c];
    }
}

__global__ void syrk_kernel(int j1) {
    __shared__ float Pi[16 * 65], Pk[16 * 65];
    const int j0 = j1 - 64;
    int tx = threadIdx.x, ty = threadIdx.y;
    int tid = ty * 16 + tx;
    int i = j1 + blockIdx.y * 16 + ty;
    int k = j1 + blockIdx.x * 16 + tx;
    for (int e = tid; e < 16 * 64; e += 256) {
        int r = e >> 6, l = e & 63;
        Pi[r * 65 + l] = g_Kss[(size_t)(j1 + blockIdx.y * 16 + r) * NS + j0 + l];
        Pk[r * 65 + l] = g_Kss[(size_t)(j1 + blockIdx.x * 16 + r) * NS + j0 + l];
    }
    __syncthreads();
    float acc = 0.f;
    #pragma unroll
    for (int l = 0; l < 64; ++l) acc += Pi[ty * 65 + l] * Pk[tx * 65 + l];
    g_Kss[(size_t)i * NS + k] -= acc;
}

// ---------------------------------------------------------------------------
// 4) transpose L (for coalesced backward solve)
// ---------------------------------------------------------------------------
__global__ void transpose_kernel() {
    __shared__ float t[32][33];
    int x = blockIdx.x * 32 + threadIdx.x;
    int y = blockIdx.y * 32 + threadIdx.y;
    #pragma unroll
    for (int j = 0; j < 32; j += 8)
        t[threadIdx.y + j][threadIdx.x] = g_Kss[(size_t)(y + j) * NS + x];
    __syncthreads();
    x = blockIdx.y * 32 + threadIdx.x;
    y = blockIdx.x * 32 + threadIdx.y;
    #pragma unroll
    for (int j = 0; j < 32; j += 8)
        g_LT[(size_t)(y + j) * NS + x] = t[threadIdx.x][threadIdx.y + j];
}

// ---------------------------------------------------------------------------
// 5) forward/backward triangular solve, 16 RHS (one-hot of Ys)
//    layout: warp w handles class c=w, lanes split k
// ---------------------------------------------------------------------------
__global__ void solve_kernel(const int* __restrict__ Ys) {
    __shared__ float y[NS * 17];            // padded rows of 17 (16 used)
    const int tid = threadIdx.x;            // 512 threads = 16 warps
    const int lane = tid & 31;
    const int c = tid >> 5;                 // class 0..15
    // forward: L y = onehot
    for (int i = 0; i < NS; ++i) {
        float part = 0.f;
        for (int k = lane; k < i; k += 32)
            part += g_Kss[(size_t)i * NS + k] * y[k * 17 + c];
        #pragma unroll
        for (int d = 16; d; d >>= 1) part += __shfl_xor_sync(0xffffffffu, part, d);
        if (lane == 0) {
            float b = (Ys[i] == c) ? 1.0f : 0.0f;
            y[i * 17 + c] = (b - part) / g_Kss[(size_t)i * NS + i];
        }
        __syncthreads();
    }
    // backward: L^T x = y (in place)
    for (int i = NS - 1; i >= 0; --i) {
        float part = 0.f;
        for (int k = i + 1 + lane; k < NS; k += 32)
            part += g_LT[(size_t)i * NS + k] * y[k * 17 + c];
        #pragma unroll
        for (int d = 16; d; d >>= 1) part += __shfl_xor_sync(0xffffffffu, part, d);
        if (lane == 0)
            y[i * 17 + c] = (y[i * 17 + c] - part) / g_Kss[(size_t)i * NS + i];
        __syncthreads();
    }
    for (int e = tid; e < NS * NW; e += 512)
        g_alpha[e] = y[(e / NW) * 17 + (e % NW)];
}

// ---------------------------------------------------------------------------
// 6) fused main kernel: Kqs tile GEMM -> exp -> @alpha -> softmax
// ---------------------------------------------------------------------------
__global__ void __launch_bounds__(256)
fused_kernel(const float* __restrict__ Zq, const float* __restrict__ Zs,
             const float* __restrict__ log_ls_p, float* __restrict__ out) {
    // smem: [ As | Bs ] overlaid with Kt (temporally disjoint)
    __shared__ float4 sbuf4[BM * BN / 4];   // 32 KB
    float* sbuf = (float*)sbuf4;
    float* As = sbuf;                       // BK * AS_STRIDE = 4224 floats
    float* Bs = sbuf + BK * AS_STRIDE;      // BK * BS_STRIDE = 2176 floats
    float* Kt = sbuf;                       // BM * BN = 8192 floats
    __shared__ float alphaT[NW * 68];       // padded [16][68]
    __shared__ float sqq[BM];
    __shared__ float sqs_sm[NS];

    const int tid = threadIdx.x;
    const int tx = tid & 15, ty = tid >> 4;
    const int q0 = blockIdx.x * BM;
    const float inv2 = 0.5f * __expf(-2.0f * (*log_ls_p));

    for (int e = tid; e < NS; e += 256) sqs_sm[e] = g_sqs[e];
    // query squared norms (2 threads per row)
    {
        int r = tid >> 1, half = tid & 1;
        const float4* zr = (const float4*)(Zq + (size_t)(q0 + r) * D) + half * (D / 8);
        float s = 0.f;
        #pragma unroll 8
        for (int t = 0; t < D / 8; ++t) {
            float4 v = zr[t];
            s += v.x * v.x + v.y * v.y + v.z * v.z + v.w * v.w;
        }
        s += __shfl_xor_sync(0xffffffffu, s, 1);
        if (half == 0) sqq[r] = s;
    }

    float f[8];
    #pragma unroll
    for (int i = 0; i < 8; ++i) f[i] = 0.f;
    const int c = tid & 15, qg = tid >> 4;

    for (int st = 0; st < NS / BN; ++st) {
        const int s0 = st * BN;
        __syncthreads();  // prev stage2 done (Kt / alphaT free)
        #pragma unroll
        for (int v = 0; v < 4; ++v) {
            int e = tid + v * 256;
            int s = e >> 4, cc = e & 15;
            alphaT[cc * 68 + s] = g_alpha[(s0 + s) * NW + cc];
        }

        float acc[8][4];
        #pragma unroll
        for (int i = 0; i < 8; ++i)
            #pragma unroll
            for (int j = 0; j < 4; ++j) acc[i][j] = 0.f;

        for (int kt = 0; kt < D; kt += BK) {
            __syncthreads();
            #pragma unroll
            for (int v = 0; v < 4; ++v) {
                int e = tid + v * 256;
                int r = e >> 3, c4 = (e & 7) * 4;
                float4 val = *(const float4*)(Zq + (size_t)(q0 + r) * D + kt + c4);
                As[(c4 + 0) * AS_STRIDE + r] = val.x;
                As[(c4 + 1) * AS_STRIDE + r] = val.y;
                As[(c4 + 2) * AS_STRIDE + r] = val.z;
                As[(c4 + 3) * AS_STRIDE + r] = val.w;
            }
            #pragma unroll
            for (int v = 0; v < 2; ++v) {
                int e = tid + v * 256;
                int r = e >> 3, c4 = (e & 7) * 4;
                float4 val = *(const float4*)(Zs + (size_t)(s0 + r) * D + kt + c4);
                Bs[(c4 + 0) * BS_STRIDE + r] = val.x;
                Bs[(c4 + 1) * BS_STRIDE + r] = val.y;
                Bs[(c4 + 2) * BS_STRIDE + r] = val.z;
                Bs[(c4 + 3) * BS_STRIDE + r] = val.w;
            }
            __syncthreads();
            #pragma unroll
            for (int k = 0; k < BK; ++k) {
                float4 m0 = *(const float4*)&As[k * AS_STRIDE + ty * 8];
                float4 m1 = *(const float4*)&As[k * AS_STRIDE + ty * 8 + 4];
                float4 nv = *(const float4*)&Bs[k * BS_STRIDE + tx * 4];
                float mr[8] = {m0.x, m0.y, m0.z, m0.w, m1.x, m1.y, m1.z, m1.w};
                float nr[4] = {nv.x, nv.y, nv.z, nv.w};
                #pragma unroll
                for (int i = 0; i < 8; ++i)
                    #pragma unroll
                    for (int j = 0; j < 4; ++j) acc[i][j] += mr[i] * nr[j];
            }
        }
        __syncthreads();  // As/Bs consumed; Kt region free to write
        #pragma unroll
        for (int i = 0; i < 8; ++i) {
            int q = ty * 8 + i;
            float sq = sqq[q];
            float4 kv;
            kv.x = __expf(-fmaxf(sq + sqs_sm[s0 + tx * 4 + 0] - 2.f * acc[i][0], 0.f) * inv2);
            kv.y = __expf(-fmaxf(sq + sqs_sm[s0 + tx * 4 + 1] - 2.f * acc[i][1], 0.f) * inv2);
            kv.z = __expf(-fmaxf(sq + sqs_sm[s0 + tx * 4 + 2] - 2.f * acc[i][2], 0.f) * inv2);
            kv.w = __expf(-fmaxf(sq + sqs_sm[s0 + tx * 4 + 3] - 2.f * acc[i][3], 0.f) * inv2);
            *(float4*)&Kt[q * BN + tx * 4] = kv;
        }
        __syncthreads();
        // stage2: f[q][c] += K[q][s] * alpha[s][c]
        #pragma unroll
        for (int s4 = 0; s4 < BN / 4; ++s4) {
            float4 av = *(const float4*)&alphaT[c * 68 + s4 * 4];
            #pragma unroll
            for (int i = 0; i < 8; ++i) {
                float4 kv = *(const float4*)&Kt[(qg + 16 * i) * BN + s4 * 4];
                f[i] += kv.x * av.x + kv.y * av.y + kv.z * av.z + kv.w * av.w;
            }
        }
    }
    // softmax over 16 classes (16-lane shuffle groups)
    #pragma unroll
    for (int i = 0; i < 8; ++i) {
        float mx = f[i];
        #pragma unroll
        for (int d = 8; d; d >>= 1) mx = fmaxf(mx, __shfl_xor_sync(0xffffffffu, mx, d));
        float e = __expf(f[i] - mx);
        float sm = e;
        #pragma unroll
        for (int d = 8; d; d >>= 1) sm += __shfl_xor_sync(0xffffffffu, sm, d);
        out[(size_t)(q0 + qg + 16 * i) * NW + c] = e / sm;
    }
}

// ---------------------------------------------------------------------------
extern "C" void kernel_launch(void* const* d_in, const int* in_sizes, int n_in,
                              void* d_out, int out_size) {
    const float* Zs = (const float*)d_in[0];
    const int*   Ys = (const int*)d_in[1];
    const float* Zq = (const float*)d_in[2];
    const float* log_ls = (const float*)d_in[3];
    const float* log_noise = (const float*)d_in[4];

    int Nsamp = in_sizes[1];                 // 512
    int Dh = in_sizes[0] / Nsamp;            // 1024
    int Q = in_sizes[2] / Dh;                // 65536
    (void)n_in; (void)out_size; (void)Nsamp; (void)Dh;

    sqs_kernel<<<NS, 256>>>(Zs);
    kss_kernel<<<dim3(NS / 16, NS / 16), dim3(16, 16)>>>(Zs, log_ls, log_noise);

    cudaFuncSetAttribute(chol_panel_kernel,
                         cudaFuncAttributeMaxDynamicSharedMemorySize, NS * 65 * 4);
    for (int p = 0; p < NS / 64; ++p) {
        int rows = NS - p * 64;
        chol_panel_kernel<<<1, 1024, rows * 65 * sizeof(float)>>>(p);
        int j1 = p * 64 + 64;
        if (j1 < NS) {
            int m = NS - j1;
            syrk_kernel<<<dim3(m / 16, m / 16), dim3(16, 16)>>>(j1);
        }
    }
    transpose_kernel<<<dim3(NS / 32, NS / 32), dim3(32, 8)>>>();
    solve_kernel<<<1, 512>>>(Ys);

    fused_kernel<<<Q / BM, 256>>>(Zq, Zs, log_ls, (float*)d_out);
}

// round 2
// speedup vs baseline: 1.0045x; 1.0045x over previous
#include <cuda_runtime.h>
#include <cuda_bf16.h>
#include <math.h>

// Problem constants (fixed dataset: N_way=16, K_shot=32, Q=65536, D=1024)
constexpr int NS = 512;   // support samples
constexpr int D  = 1024;  // feature dim
constexpr int NW = 16;    // classes

// Fused-kernel tiling
constexpr int BM = 128;   // queries per block
constexpr int BN = 64;    // support per s-tile
constexpr int BK = 32;    // k-tile
constexpr int AS_STRIDE = BM + 4;  // 132
constexpr int BS_STRIDE = BN + 4;  // 68

// Scratch (device globals; no allocations allowed)
__device__ float g_Kss[NS * NS];
__device__ float g_LT[NS * NS];
__device__ float g_alpha[NS * NW];
__device__ float g_sqs[NS];

// ---------------------------------------------------------------------------
// 1) squared norms of support rows
// ---------------------------------------------------------------------------
__global__ void sqs_kernel(const float* __restrict__ Zs) {
    int i = blockIdx.x;
    int tid = threadIdx.x;                  // 256 threads
    const float4* z = (const float4*)(Zs + (size_t)i * D);
    float s = 0.f;
    for (int t = tid; t < D / 4; t += 256) {
        float4 v = z[t];
        s += v.x * v.x + v.y * v.y + v.z * v.z + v.w * v.w;
    }
    #pragma unroll
    for (int d = 16; d; d >>= 1) s += __shfl_xor_sync(0xffffffffu, s, d);
    __shared__ float r[8];
    if ((tid & 31) == 0) r[tid >> 5] = s;
    __syncthreads();
    if (tid == 0) {
        float t = 0.f;
        #pragma unroll
        for (int j = 0; j < 8; ++j) t += r[j];
        g_sqs[i] = t;
    }
}

// ---------------------------------------------------------------------------
// 2) Kss = rbf(Zs,Zs) + noise*I
// ---------------------------------------------------------------------------
__global__ void kss_kernel(const float* __restrict__ Zs,
                           const float* __restrict__ log_ls_p,
                           const float* __restrict__ log_noise_p) {
    __shared__ float a[16][17], b[16][17];
    int tx = threadIdx.x, ty = threadIdx.y;
    int row = blockIdx.y * 16 + ty;
    int col = blockIdx.x * 16 + tx;
    float acc = 0.f;
    for (int kt = 0; kt < D; kt += 16) {
        a[ty][tx] = Zs[(size_t)row * D + kt + tx];
        b[ty][tx] = Zs[(size_t)(blockIdx.x * 16 + ty) * D + kt + tx];
        __syncthreads();
        #pragma unroll
        for (int k = 0; k < 16; ++k) acc += a[ty][k] * b[tx][k];
        __syncthreads();
    }
    float inv2  = 0.5f * __expf(-2.0f * (*log_ls_p));
    float noise = __expf(2.0f * (*log_noise_p));
    float d2 = fmaxf(g_sqs[row] + g_sqs[col] - 2.0f * acc, 0.0f);
    float v = __expf(-d2 * inv2) + (row == col ? noise : 0.0f);
    g_Kss[row * NS + col] = v;
}

// ---------------------------------------------------------------------------
// 3) Blocked Cholesky: panel (in smem) + trailing SYRK
// ---------------------------------------------------------------------------
__global__ void chol_panel_kernel(int p) {
    extern __shared__ float P[];            // [rows][65]
    const int j0 = p * 64;
    const int rows = NS - j0;
    const int tid = threadIdx.x;            // 1024 threads
    for (int e = tid; e < rows * 64; e += 1024) {
        int r = e >> 6, c = e & 63;
        P[r * 65 + c] = g_Kss[(size_t)(j0 + r) * NS + j0 + c];
    }
    __syncthreads();
    __shared__ float sinv;
    for (int jl = 0; jl < 64; ++jl) {
        if (tid == 0) {
            float s = sqrtf(P[jl * 65 + jl]);
            P[jl * 65 + jl] = s;
            sinv = 1.0f / s;
        }
        __syncthreads();
        for (int i = jl + 1 + tid; i < rows; i += 1024) P[i * 65 + jl] *= sinv;
        __syncthreads();
        if (jl < 63) {
            int c = jl + 1 + (tid & 63);
            for (int i = jl + 1 + (tid >> 6); i < rows; i += 16) {
                if (c < 64) P[i * 65 + c] -= P[i * 65 + jl] * P[c * 65 + jl];
            }
        }
        __syncthreads();
    }
    for (int e = tid; e < rows * 64; e += 1024) {
        int r = e >> 6, c = e & 63;
        g_Kss[(size_t)(j0 + r) * NS + j0 + c] = P[r * 65 + c];
    }
}

__global__ void syrk_kernel(int j1) {
    __shared__ float Pi[16 * 65], Pk[16 * 65];
    const int j0 = j1 - 64;
    int tx = threadIdx.x, ty = threadIdx.y;
    int tid = ty * 16 + tx;
    int i = j1 + blockIdx.y * 16 + ty;
    int k = j1 + blockIdx.x * 16 + tx;
    for (int e = tid; e < 16 * 64; e += 256) {
        int r = e >> 6, l = e & 63;
        Pi[r * 65 + l] = g_Kss[(size_t)(j1 + blockIdx.y * 16 + r) * NS + j0 + l];
        Pk[r * 65 + l] = g_Kss[(size_t)(j1 + blockIdx.x * 16 + r) * NS + j0 + l];
    }
    __syncthreads();
    float acc = 0.f;
    #pragma unroll
    for (int l = 0; l < 64; ++l) acc += Pi[ty * 65 + l] * Pk[tx * 65 + l];
    g_Kss[(size_t)i * NS + k] -= acc;
}

// ---------------------------------------------------------------------------
// 4) transpose L (for coalesced backward solve)
// ---------------------------------------------------------------------------
__global__ void transpose_kernel() {
    __shared__ float t[32][33];
    int x = blockIdx.x * 32 + threadIdx.x;
    int y = blockIdx.y * 32 + threadIdx.y;
    #pragma unroll
    for (int j = 0; j < 32; j += 8)
        t[threadIdx.y + j][threadIdx.x] = g_Kss[(size_t)(y + j) * NS + x];
    __syncthreads();
    x = blockIdx.y * 32 + threadIdx.x;
    y = blockIdx.x * 32 + threadIdx.y;
    #pragma unroll
    for (int j = 0; j < 32; j += 8)
        g_LT[(size_t)(y + j) * NS + x] = t[threadIdx.x][threadIdx.y + j];
}

// ---------------------------------------------------------------------------
// 5) forward/backward triangular solve, 16 RHS (one-hot of Ys)
//    layout: warp w handles class c=w, lanes split k
// ---------------------------------------------------------------------------
__global__ void solve_kernel(const int* __restrict__ Ys) {
    __shared__ float y[NS * 17];            // padded rows of 17 (16 used)
    const int tid = threadIdx.x;            // 512 threads = 16 warps
    const int lane = tid & 31;
    const int c = tid >> 5;                 // class 0..15
    // forward: L y = onehot
    for (int i = 0; i < NS; ++i) {
        float part = 0.f;
        for (int k = lane; k < i; k += 32)
            part += g_Kss[(size_t)i * NS + k] * y[k * 17 + c];
        #pragma unroll
        for (int d = 16; d; d >>= 1) part += __shfl_xor_sync(0xffffffffu, part, d);
        if (lane == 0) {
            float b = (Ys[i] == c) ? 1.0f : 0.0f;
            y[i * 17 + c] = (b - part) / g_Kss[(size_t)i * NS + i];
        }
        __syncthreads();
    }
    // backward: L^T x = y (in place)
    for (int i = NS - 1; i >= 0; --i) {
        float part = 0.f;
        for (int k = i + 1 + lane; k < NS; k += 32)
            part += g_LT[(size_t)i * NS + k] * y[k * 17 + c];
        #pragma unroll
        for (int d = 16; d; d >>= 1) part += __shfl_xor_sync(0xffffffffu, part, d);
        if (lane == 0)
            y[i * 17 + c] = (y[i * 17 + c] - part) / g_Kss[(size_t)i * NS + i];
        __syncthreads();
    }
    for (int e = tid; e < NS * NW; e += 512)
        g_alpha[e] = y[(e / NW) * 17 + (e % NW)];
}

// ---------------------------------------------------------------------------
// 6) fused main kernel: Kqs tile GEMM -> exp -> @alpha -> softmax
// ---------------------------------------------------------------------------
__global__ void __launch_bounds__(256)
fused_kernel(const float* __restrict__ Zq, const float* __restrict__ Zs,
             const float* __restrict__ log_ls_p, float* __restrict__ out) {
    // smem: [ As | Bs ] overlaid with Kt (temporally disjoint)
    __shared__ float4 sbuf4[BM * BN / 4];   // 32 KB
    float* sbuf = (float*)sbuf4;
    float* As = sbuf;                       // BK * AS_STRIDE = 4224 floats
    float* Bs = sbuf + BK * AS_STRIDE;      // BK * BS_STRIDE = 2176 floats
    float* Kt = sbuf;                       // BM * BN = 8192 floats
    __shared__ float alphaT[NW * 68];       // padded [16][68]
    __shared__ float sqq[BM];
    __shared__ float sqs_sm[NS];

    const int tid = threadIdx.x;
    const int tx = tid & 15, ty = tid >> 4;
    const int q0 = blockIdx.x * BM;
    const float inv2 = 0.5f * __expf(-2.0f * (*log_ls_p));

    for (int e = tid; e < NS; e += 256) sqs_sm[e] = g_sqs[e];
    // query squared norms (2 threads per row)
    {
        int r = tid >> 1, half = tid & 1;
        const float4* zr = (const float4*)(Zq + (size_t)(q0 + r) * D) + half * (D / 8);
        float s = 0.f;
        #pragma unroll 8
        for (int t = 0; t < D / 8; ++t) {
            float4 v = zr[t];
            s += v.x * v.x + v.y * v.y + v.z * v.z + v.w * v.w;
        }
        s += __shfl_xor_sync(0xffffffffu, s, 1);
        if (half == 0) sqq[r] = s;
    }

    float f[8];
    #pragma unroll
    for (int i = 0; i < 8; ++i) f[i] = 0.f;
    const int c = tid & 15, qg = tid >> 4;

    for (int st = 0; st < NS / BN; ++st) {
        const int s0 = st * BN;
        __syncthreads();  // prev stage2 done (Kt / alphaT free)
        #pragma unroll
        for (int v = 0; v < 4; ++v) {
            int e = tid + v * 256;
            int s = e >> 4, cc = e & 15;
            alphaT[cc * 68 + s] = g_alpha[(s0 + s) * NW + cc];
        }

        float acc[8][4];
        #pragma unroll
        for (int i = 0; i < 8; ++i)
            #pragma unroll
            for (int j = 0; j < 4; ++j) acc[i][j] = 0.f;

        for (int kt = 0; kt < D; kt += BK) {
            __syncthreads();
            #pragma unroll
            for (int v = 0; v < 4; ++v) {
                int e = tid + v * 256;
                int r = e >> 3, c4 = (e & 7) * 4;
                float4 val = *(const float4*)(Zq + (size_t)(q0 + r) * D + kt + c4);
                As[(c4 + 0) * AS_STRIDE + r] = val.x;
                As[(c4 + 1) * AS_STRIDE + r] = val.y;
                As[(c4 + 2) * AS_STRIDE + r] = val.z;
                As[(c4 + 3) * AS_STRIDE + r] = val.w;
            }
            #pragma unroll
            for (int v = 0; v < 2; ++v) {
                int e = tid + v * 256;
                int r = e >> 3, c4 = (e & 7) * 4;
                float4 val = *(const float4*)(Zs + (size_t)(s0 + r) * D + kt + c4);
                Bs[(c4 + 0) * BS_STRIDE + r] = val.x;
                Bs[(c4 + 1) * BS_STRIDE + r] = val.y;
                Bs[(c4 + 2) * BS_STRIDE + r] = val.z;
                Bs[(c4 + 3) * BS_STRIDE + r] = val.w;
            }
            __syncthreads();
            #pragma unroll
            for (int k = 0; k < BK; ++k) {
                float4 m0 = *(const float4*)&As[k * AS_STRIDE + ty * 8];
                float4 m1 = *(const float4*)&As[k * AS_STRIDE + ty * 8 + 4];
                float4 nv = *(const float4*)&Bs[k * BS_STRIDE + tx * 4];
                float mr[8] = {m0.x, m0.y, m0.z, m0.w, m1.x, m1.y, m1.z, m1.w};
                float nr[4] = {nv.x, nv.y, nv.z, nv.w};
                #pragma unroll
                for (int i = 0; i < 8; ++i)
                    #pragma unroll
                    for (int j = 0; j < 4; ++j) acc[i][j] += mr[i] * nr[j];
            }
        }
        __syncthreads();  // As/Bs consumed; Kt region free to write
        #pragma unroll
        for (int i = 0; i < 8; ++i) {
            int q = ty * 8 + i;
            float sq = sqq[q];
            float4 kv;
            kv.x = __expf(-fmaxf(sq + sqs_sm[s0 + tx * 4 + 0] - 2.f * acc[i][0], 0.f) * inv2);
            kv.y = __expf(-fmaxf(sq + sqs_sm[s0 + tx * 4 + 1] - 2.f * acc[i][1], 0.f) * inv2);
            kv.z = __expf(-fmaxf(sq + sqs_sm[s0 + tx * 4 + 2] - 2.f * acc[i][2], 0.f) * inv2);
            kv.w = __expf(-fmaxf(sq + sqs_sm[s0 + tx * 4 + 3] - 2.f * acc[i][3], 0.f) * inv2);
            *(float4*)&Kt[q * BN + tx * 4] = kv;
        }
        __syncthreads();
        // stage2: f[q][c] += K[q][s] * alpha[s][c]
        #pragma unroll
        for (int s4 = 0; s4 < BN / 4; ++s4) {
            float4 av = *(const float4*)&alphaT[c * 68 + s4 * 4];
            #pragma unroll
            for (int i = 0; i < 8; ++i) {
                float4 kv = *(const float4*)&Kt[(qg + 16 * i) * BN + s4 * 4];
                f[i] += kv.x * av.x + kv.y * av.y + kv.z * av.z + kv.w * av.w;
            }
        }
    }
    // softmax over 16 classes (16-lane shuffle groups)
    #pragma unroll
    for (int i = 0; i < 8; ++i) {
        float mx = f[i];
        #pragma unroll
        for (int d = 8; d; d >>= 1) mx = fmaxf(mx, __shfl_xor_sync(0xffffffffu, mx, d));
        float e = __expf(f[i] - mx);
        float sm = e;
        #pragma unroll
        for (int d = 8; d; d >>= 1) sm += __shfl_xor_sync(0xffffffffu, sm, d);
        out[(size_t)(q0 + qg + 16 * i) * NW + c] = e / sm;
    }
}

// ---------------------------------------------------------------------------
extern "C" void kernel_launch(void* const* d_in, const int* in_sizes, int n_in,
                              void* d_out, int out_size) {
    const float* Zs = (const float*)d_in[0];
    const int*   Ys = (const int*)d_in[1];
    const float* Zq = (const float*)d_in[2];
    const float* log_ls = (const float*)d_in[3];
    const float* log_noise = (const float*)d_in[4];

    int Nsamp = in_sizes[1];                 // 512
    int Dh = in_sizes[0] / Nsamp;            // 1024
    int Q = in_sizes[2] / Dh;                // 65536
    (void)n_in; (void)out_size; (void)Nsamp; (void)Dh;

    sqs_kernel<<<NS, 256>>>(Zs);
    kss_kernel<<<dim3(NS / 16, NS / 16), dim3(16, 16)>>>(Zs, log_ls, log_noise);

    cudaFuncSetAttribute(chol_panel_kernel,
                         cudaFuncAttributeMaxDynamicSharedMemorySize, NS * 65 * 4);
    for (int p = 0; p < NS / 64; ++p) {
        int rows = NS - p * 64;
        chol_panel_kernel<<<1, 1024, rows * 65 * sizeof(float)>>>(p);
        int j1 = p * 64 + 64;
        if (j1 < NS) {
            int m = NS - j1;
            syrk_kernel<<<dim3(m / 16, m / 16), dim3(16, 16)>>>(j1);
        }
    }
    transpose_kernel<<<dim3(NS / 32, NS / 32), dim3(32, 8)>>>();
    solve_kernel<<<1, 512>>>(Ys);

    fused_kernel<<<Q / BM, 256>>>(Zq, Zs, log_ls, (float*)d_out);
}

// round 4
// speedup vs baseline: 2.7531x; 2.7407x over previous
#include <cuda_runtime.h>
#include <cuda_bf16.h>
#include <math.h>
#include <stdint.h>

constexpr int NS = 512;    // support samples
constexpr int D  = 1024;   // feature dim
constexpr int NW = 16;     // classes
constexpr int QN = 65536;  // queries

// ---------------------------------------------------------------------------
// Device-global scratch (no allocations allowed)
// ---------------------------------------------------------------------------
__device__ float g_Kss[NS * NS];
__device__ float g_LT[NS * NS];
__device__ float g_sqs[NS];
__device__ float g_sqq[QN];
__device__ __align__(16) __nv_bfloat16 g_alpha_bf[NS * NW];
// bf16, K-chunked (64 elems = 128B per row-chunk) + XOR-swizzled 16B chunks
__device__ uint4 g_Zq_r[(size_t)QN * 128];
__device__ uint4 g_Zs_r[(size_t)NS * 128];

// ---------------------------------------------------------------------------
// sm_80-compatible PTX helpers (NO tcgen05 — harness compiles at sm_100)
// ---------------------------------------------------------------------------
__device__ __forceinline__ uint32_t smem_u32(const void* p) {
    uint32_t a;
    asm("{ .reg .u64 t; cvta.to.shared.u64 t, %1; cvt.u32.u64 %0, t; }" : "=r"(a) : "l"(p));
    return a;
}
__device__ __forceinline__ void cp_async16(uint32_t dst, const void* src) {
    asm volatile("cp.async.cg.shared.global [%0], [%1], 16;" :: "r"(dst), "l"(src));
}
__device__ __forceinline__ void ldsm_x4(uint32_t& r0, uint32_t& r1, uint32_t& r2, uint32_t& r3,
                                        uint32_t addr) {
    asm volatile("ldmatrix.sync.aligned.m8n8.x4.shared.b16 {%0,%1,%2,%3}, [%4];"
                 : "=r"(r0), "=r"(r1), "=r"(r2), "=r"(r3) : "r"(addr));
}
__device__ __forceinline__ void ldsm_x4_t(uint32_t& r0, uint32_t& r1, uint32_t& r2, uint32_t& r3,
                                          uint32_t addr) {
    asm volatile("ldmatrix.sync.aligned.m8n8.x4.trans.shared.b16 {%0,%1,%2,%3}, [%4];"
                 : "=r"(r0), "=r"(r1), "=r"(r2), "=r"(r3) : "r"(addr));
}
__device__ __forceinline__ void mma_bf16(float* c, uint32_t a0, uint32_t a1, uint32_t a2,
                                         uint32_t a3, uint32_t b0, uint32_t b1) {
    asm volatile(
        "mma.sync.aligned.m16n8k16.row.col.f32.bf16.bf16.f32 "
        "{%0,%1,%2,%3}, {%4,%5,%6,%7}, {%8,%9}, {%0,%1,%2,%3};"
        : "+f"(c[0]), "+f"(c[1]), "+f"(c[2]), "+f"(c[3])
        : "r"(a0), "r"(a1), "r"(a2), "r"(a3), "r"(b0), "r"(b1));
}
__device__ __forceinline__ uint32_t pack_bf16(float lo, float hi) {
    uint32_t r;
    asm("cvt.rn.bf16x2.f32 %0, %1, %2;" : "=r"(r) : "f"(hi), "f"(lo));
    return r;
}

// ---------------------------------------------------------------------------
// 0) fp32 -> bf16 K-chunked swizzled layout + row sq-norms (warp per row)
// ---------------------------------------------------------------------------
__global__ void convert_kernel(const float* __restrict__ Z, int nrows, int is_q) {
    uint4* outv = is_q ? g_Zq_r : g_Zs_r;
    float* sq   = is_q ? g_sqq  : g_sqs;
    const int row = (blockIdx.x * blockDim.x + threadIdx.x) >> 5;
    const int lane = threadIdx.x & 31;
    if (row >= nrows) return;
    const float4* src = (const float4*)(Z + (size_t)row * D);
    float ss = 0.f;
    #pragma unroll
    for (int it = 0; it < 4; ++it) {
        int m = it * 32 + lane;            // 16B-chunk id 0..127
        int kt = m >> 3, c16 = m & 7;
        float4 a = src[m * 2], b = src[m * 2 + 1];
        ss += a.x*a.x + a.y*a.y + a.z*a.z + a.w*a.w
            + b.x*b.x + b.y*b.y + b.z*b.z + b.w*b.w;
        uint4 o;
        o.x = pack_bf16(a.x, a.y); o.y = pack_bf16(a.z, a.w);
        o.z = pack_bf16(b.x, b.y); o.w = pack_bf16(b.z, b.w);
        outv[((size_t)kt * nrows + row) * 8 + (c16 ^ (row & 7))] = o;
    }
    #pragma unroll
    for (int d = 16; d; d >>= 1) ss += __shfl_xor_sync(0xffffffffu, ss, d);
    if (lane == 0) sq[row] = ss;
}

// ---------------------------------------------------------------------------
// 1) Kss = rbf(Zs,Zs) + noise*I
// ---------------------------------------------------------------------------
__global__ void kss_kernel(const float* __restrict__ Zs,
                           const float* __restrict__ log_ls_p,
                           const float* __restrict__ log_noise_p) {
    __shared__ float a[16][17], b[16][17];
    int tx = threadIdx.x, ty = threadIdx.y;
    int row = blockIdx.y * 16 + ty;
    int col = blockIdx.x * 16 + tx;
    float acc = 0.f;
    for (int kt = 0; kt < D; kt += 16) {
        a[ty][tx] = Zs[(size_t)row * D + kt + tx];
        b[ty][tx] = Zs[(size_t)(blockIdx.x * 16 + ty) * D + kt + tx];
        __syncthreads();
        #pragma unroll
        for (int k = 0; k < 16; ++k) acc += a[ty][k] * b[tx][k];
        __syncthreads();
    }
    float inv2  = 0.5f * __expf(-2.0f * (*log_ls_p));
    float noise = __expf(2.0f * (*log_noise_p));
    float d2 = fmaxf(g_sqs[row] + g_sqs[col] - 2.0f * acc, 0.0f);
    g_Kss[row * NS + col] = __expf(-d2 * inv2) + (row == col ? noise : 0.0f);
}

// ---------------------------------------------------------------------------
// 2) Blocked Cholesky: panel + trailing SYRK
// ---------------------------------------------------------------------------
__global__ void chol_panel_kernel(int p) {
    extern __shared__ float P[];
    const int j0 = p * 64;
    const int rows = NS - j0;
    const int tid = threadIdx.x;
    for (int e = tid; e < rows * 64; e += 1024) {
        int r = e >> 6, c = e & 63;
        P[r * 65 + c] = g_Kss[(size_t)(j0 + r) * NS + j0 + c];
    }
    __syncthreads();
    __shared__ float sinv;
    for (int jl = 0; jl < 64; ++jl) {
        if (tid == 0) {
            float s = sqrtf(P[jl * 65 + jl]);
            P[jl * 65 + jl] = s;
            sinv = 1.0f / s;
        }
        __syncthreads();
        for (int i = jl + 1 + tid; i < rows; i += 1024) P[i * 65 + jl] *= sinv;
        __syncthreads();
        if (jl < 63) {
            int c = jl + 1 + (tid & 63);
            for (int i = jl + 1 + (tid >> 6); i < rows; i += 16) {
                if (c < 64) P[i * 65 + c] -= P[i * 65 + jl] * P[c * 65 + jl];
            }
        }
        __syncthreads();
    }
    for (int e = tid; e < rows * 64; e += 1024) {
        int r = e >> 6, c = e & 63;
        g_Kss[(size_t)(j0 + r) * NS + j0 + c] = P[r * 65 + c];
    }
}

__global__ void syrk_kernel(int j1) {
    __shared__ float Pi[16 * 65], Pk[16 * 65];
    const int j0 = j1 - 64;
    int tx = threadIdx.x, ty = threadIdx.y;
    int tid = ty * 16 + tx;
    int i = j1 + blockIdx.y * 16 + ty;
    int k = j1 + blockIdx.x * 16 + tx;
    for (int e = tid; e < 16 * 64; e += 256) {
        int r = e >> 6, l = e & 63;
        Pi[r * 65 + l] = g_Kss[(size_t)(j1 + blockIdx.y * 16 + r) * NS + j0 + l];
        Pk[r * 65 + l] = g_Kss[(size_t)(j1 + blockIdx.x * 16 + r) * NS + j0 + l];
    }
    __syncthreads();
    float acc = 0.f;
    #pragma unroll
    for (int l = 0; l < 64; ++l) acc += Pi[ty * 65 + l] * Pk[tx * 65 + l];
    g_Kss[(size_t)i * NS + k] -= acc;
}

__global__ void transpose_kernel() {
    __shared__ float t[32][33];
    int x = blockIdx.x * 32 + threadIdx.x;
    int y = blockIdx.y * 32 + threadIdx.y;
    #pragma unroll
    for (int j = 0; j < 32; j += 8)
        t[threadIdx.y + j][threadIdx.x] = g_Kss[(size_t)(y + j) * NS + x];
    __syncthreads();
    x = blockIdx.y * 32 + threadIdx.x;
    y = blockIdx.x * 32 + threadIdx.y;
    #pragma unroll
    for (int j = 0; j < 32; j += 8)
        g_LT[(size_t)(y + j) * NS + x] = t[threadIdx.x][threadIdx.y + j];
}

// ---------------------------------------------------------------------------
// 3) Blocked triangular solves: diag blocks in smem, warp-per-class serial part
// ---------------------------------------------------------------------------
constexpr int YST = 521;
constexpr int SOLVE_SMEM = (16 * YST + 64 * 65 + 16 * 64) * 4 + 512 * 4;

__global__ void __launch_bounds__(1024) solve2_kernel(const int* __restrict__ Ys) {
    extern __shared__ float ssm[];
    float* yT   = ssm;                     // [16][YST]
    float* Ld   = ssm + 16 * YST;          // [64][65]
    float* part = Ld + 64 * 65;            // [16][64]
    int*   ysm  = (int*)(part + 16 * 64);  // [512]
    const int tid = threadIdx.x, w = tid >> 5, lane = tid & 31;
    for (int i = tid; i < NS; i += 1024) ysm[i] = Ys[i];
    __syncthreads();
    // forward: L y = onehot
    for (int bi = 0; bi < 8; ++bi) {
        const int i0 = bi * 64;
        {
            int r = tid >> 4, c = tid & 15;
            float p = 0.f;
            const float* Lr = g_Kss + (size_t)(i0 + r) * NS;
            for (int k = 0; k < i0; ++k) p += Lr[k] * yT[c * YST + k];
            part[c * 64 + r] = p;
        }
        for (int e = tid; e < 64 * 64; e += 1024) {
            int r = e >> 6, cc = e & 63;
            Ld[r * 65 + cc] = g_Kss[(size_t)(i0 + r) * NS + i0 + cc];
        }
        __syncthreads();
        if (w < 16) {
            const int c = w;
            for (int il = 0; il < 64; ++il) {
                float s = 0.f;
                for (int j = lane; j < il; j += 32)
                    s += Ld[il * 65 + j] * yT[c * YST + i0 + j];
                #pragma unroll
                for (int d = 16; d; d >>= 1) s += __shfl_xor_sync(0xffffffffu, s, d);
                if (lane == 0) {
                    float b = (ysm[i0 + il] == c) ? 1.0f : 0.0f;
                    yT[c * YST + i0 + il] = (b - part[c * 64 + il] - s) / Ld[il * 65 + il];
                }
                __syncwarp();
            }
        }
        __syncthreads();
    }
    // backward: L^T x = y
    for (int bi = 7; bi >= 0; --bi) {
        const int i0 = bi * 64, i1 = i0 + 64;
        {
            int r = tid >> 4, c = tid & 15;
            float p = 0.f;
            const float* Lr = g_LT + (size_t)(i0 + r) * NS;
            for (int k = i1; k < NS; ++k) p += Lr[k] * yT[c * YST + k];
            part[c * 64 + r] = p;
        }
        for (int e = tid; e < 64 * 64; e += 1024) {
            int r = e >> 6, cc = e & 63;
            Ld[r * 65 + cc] = g_LT[(size_t)(i0 + r) * NS + i0 + cc];
        }
        __syncthreads();
        if (w < 16) {
            const int c = w;
            for (int il = 63; il >= 0; --il) {
                float s = 0.f;
                for (int j = il + 1 + lane; j < 64; j += 32)
                    s += Ld[il * 65 + j] * yT[c * YST + i0 + j];
                #pragma unroll
                for (int d = 16; d; d >>= 1) s += __shfl_xor_sync(0xffffffffu, s, d);
                if (lane == 0)
                    yT[c * YST + i0 + il] =
                        (yT[c * YST + i0 + il] - part[c * 64 + il] - s) / Ld[il * 65 + il];
                __syncwarp();
            }
        }
        __syncthreads();
    }
    for (int e = tid; e < NS * NW; e += 1024)
        g_alpha_bf[e] = __float2bfloat16(yT[(e & 15) * YST + (e >> 4)]);
}

// ---------------------------------------------------------------------------
// 4) fused main kernel: HMMA GEMM (128 x 512 x 1024) -> exp -> HMMA @alpha -> softmax
// ---------------------------------------------------------------------------
constexpr int NST = 4;
constexpr int STG_BYTES = 32768;                 // A 16KB + B 16KB per stage
constexpr int OFF_KV   = NST * STG_BYTES;        // 131072, 32KB kv tile
constexpr int OFF_AL   = OFF_KV + 32768;         // 163840, 512 x 48B alpha
constexpr int OFF_FRED = OFF_AL + 512 * 48;      // 188416, 128 x 17 fp32
constexpr int OFF_SQQ  = OFF_FRED + 128 * 17 * 4;  // 197120
constexpr int OFF_SQS  = OFF_SQQ + 512;          // 197632
constexpr int FUSED_SMEM = OFF_SQS + 2048;       // 199680

__global__ void __launch_bounds__(256, 1)
fused_hmma_kernel(const float* __restrict__ log_ls_p, float* __restrict__ out) {
    extern __shared__ __align__(16) char sm[];
    const uint32_t sb = smem_u32(sm);
    float* sqq  = (float*)(sm + OFF_SQQ);
    float* sqs  = (float*)(sm + OFF_SQS);
    float* fred = (float*)(sm + OFF_FRED);
    const int tid = threadIdx.x, lane = tid & 31, w = tid >> 5;
    const int q0 = blockIdx.x * 128;
    const int wm = w & 3, wn = w >> 2;           // row-block 32, col-block 64
    const int jr = lane & 7, jg = lane >> 3;     // ldmatrix address lane roles
    const float inv2 = 0.5f * __expf(-2.0f * (*log_ls_p));

    // preload sqq/sqs/alpha into smem
    for (int i = tid; i < 128; i += 256) sqq[i] = g_sqq[q0 + i];
    for (int i = tid; i < 512; i += 256) sqs[i] = g_sqs[i];
    for (int i = tid; i < 1024; i += 256) {     // 1024 x 16B halves
        int s = i >> 1, h = i & 1;
        *(uint4*)(sm + OFF_AL + s * 48 + h * 16) = ((const uint4*)g_alpha_bf)[i];
    }

    auto issue = [&](int it) {
        int st = it >> 4, kt = it & 15;
        uint32_t buf = sb + (uint32_t)(it & (NST - 1)) * STG_BYTES;
        const char* Ag = (const char*)g_Zq_r + ((size_t)kt * QN + q0) * 128;
        const char* Bg = (const char*)g_Zs_r + ((size_t)kt * NS + st * 128) * 128;
        #pragma unroll
        for (int i = 0; i < 4; ++i) {
            int ch = tid + i * 256;
            cp_async16(buf + ch * 16, Ag + ch * 16);
        }
        #pragma unroll
        for (int i = 0; i < 4; ++i) {
            int ch = tid + i * 256;
            cp_async16(buf + 16384 + ch * 16, Bg + ch * 16);
        }
        asm volatile("cp.async.commit_group;");
    };
    issue(0); issue(1); issue(2);

    float acc[2][8][4];
    float acc2[2][4] = {0.f, 0.f, 0.f, 0.f, 0.f, 0.f, 0.f, 0.f};

    #pragma unroll 1
    for (int it = 0; it < 64; ++it) {
        const int kt = it & 15, st = it >> 4;
        if (kt == 0) {
            #pragma unroll
            for (int rt = 0; rt < 2; ++rt)
                #pragma unroll
                for (int ct = 0; ct < 8; ++ct)
                    #pragma unroll
                    for (int e = 0; e < 4; ++e) acc[rt][ct][e] = 0.f;
        }
        if (it <= 60) asm volatile("cp.async.wait_group 2;");
        else          asm volatile("cp.async.wait_group 0;");
        __syncthreads();

        const uint32_t Ab = sb + (uint32_t)(it & (NST - 1)) * STG_BYTES;
        const uint32_t Bb = Ab + 16384;
        #pragma unroll
        for (int ks = 0; ks < 4; ++ks) {
            uint32_t a[2][4];
            #pragma unroll
            for (int rt = 0; rt < 2; ++rt) {
                int r = wm * 32 + rt * 16 + (jg & 1) * 8 + jr;
                int c = (ks * 2 + (jg >> 1)) ^ jr;
                ldsm_x4(a[rt][0], a[rt][1], a[rt][2], a[rt][3], Ab + (r * 8 + c) * 16);
            }
            #pragma unroll
            for (int nt = 0; nt < 4; ++nt) {
                uint32_t b0, b1, b2, b3;
                int n = wn * 64 + nt * 16 + (jg >> 1) * 8 + jr;
                int c = (ks * 2 + (jg & 1)) ^ jr;
                ldsm_x4(b0, b1, b2, b3, Bb + (n * 8 + c) * 16);
                #pragma unroll
                for (int rt = 0; rt < 2; ++rt) {
                    mma_bf16(acc[rt][nt * 2],     a[rt][0], a[rt][1], a[rt][2], a[rt][3], b0, b1);
                    mma_bf16(acc[rt][nt * 2 + 1], a[rt][0], a[rt][1], a[rt][2], a[rt][3], b2, b3);
                }
            }
        }

        if (kt == 15) {
            // epilogue A: acc -> kv (bf16, swizzled) in smem
            #pragma unroll
            for (int rt = 0; rt < 2; ++rt) {
                int ql = wm * 32 + rt * 16 + (lane >> 2);
                float sqlo = sqq[ql], sqhi = sqq[ql + 8];
                #pragma unroll
                for (int ct = 0; ct < 8; ++ct) {
                    int c0 = wn * 64 + ct * 8 + (lane & 3) * 2;
                    float sa = sqs[st * 128 + c0], sc = sqs[st * 128 + c0 + 1];
                    float* cc = acc[rt][ct];
                    float k00 = __expf(-fmaxf(sqlo + sa - 2.f * cc[0], 0.f) * inv2);
                    float k01 = __expf(-fmaxf(sqlo + sc - 2.f * cc[1], 0.f) * inv2);
                    float k10 = __expf(-fmaxf(sqhi + sa - 2.f * cc[2], 0.f) * inv2);
                    float k11 = __expf(-fmaxf(sqhi + sc - 2.f * cc[3], 0.f) * inv2);
                    int chn = wn * 8 + ct, w0 = (lane & 3) * 4;
                    int qh = ql + 8;
                    *(uint32_t*)(sm + OFF_KV + (ql * 16 + (chn ^ (ql & 7))) * 16 + w0) =
                        pack_bf16(k00, k01);
                    *(uint32_t*)(sm + OFF_KV + (qh * 16 + (chn ^ (qh & 7))) * 16 + w0) =
                        pack_bf16(k10, k11);
                }
            }
            __syncthreads();
            // epilogue B: f += kv @ alpha via HMMA (warp w owns query rows w*16..+15)
            #pragma unroll
            for (int k2 = 0; k2 < 8; ++k2) {
                uint32_t a0, a1, a2, a3, b0, b1, b2, b3;
                int r = w * 16 + (jg & 1) * 8 + jr;
                int c = (k2 * 2 + (jg >> 1)) ^ jr;
                ldsm_x4(a0, a1, a2, a3, sb + OFF_KV + (r * 16 + c) * 16);
                int s = st * 128 + k2 * 16 + (jg & 1) * 8 + jr;
                int h = jg >> 1;
                ldsm_x4_t(b0, b1, b2, b3, sb + OFF_AL + s * 48 + h * 16);
                mma_bf16(acc2[0], a0, a1, a2, a3, b0, b1);
                mma_bf16(acc2[1], a0, a1, a2, a3, b2, b3);
            }
            __syncthreads();
        }
        if (it + 3 < 64) issue(it + 3);
    }

    // gather logits and softmax
    {
        int r = w * 16 + (lane >> 2);
        #pragma unroll
        for (int ct = 0; ct < 2; ++ct) {
            int c0 = ct * 8 + (lane & 3) * 2;
            fred[r * 17 + c0]           = acc2[ct][0];
            fred[r * 17 + c0 + 1]       = acc2[ct][1];
            fred[(r + 8) * 17 + c0]     = acc2[ct][2];
            fred[(r + 8) * 17 + c0 + 1] = acc2[ct][3];
        }
    }
    __syncthreads();
    if (tid < 128) {
        float f[16];
        #pragma unroll
        for (int c = 0; c < 16; ++c) f[c] = fred[tid * 17 + c];
        float mx = f[0];
        #pragma unroll
        for (int c = 1; c < 16; ++c) mx = fmaxf(mx, f[c]);
        float sum = 0.f;
        #pragma unroll
        for (int c = 0; c < 16; ++c) { f[c] = __expf(f[c] - mx); sum += f[c]; }
        float inv = 1.0f / sum;
        float4* o = (float4*)(out + (size_t)(q0 + tid) * 16);
        o[0] = make_float4(f[0] * inv,  f[1] * inv,  f[2] * inv,  f[3] * inv);
        o[1] = make_float4(f[4] * inv,  f[5] * inv,  f[6] * inv,  f[7] * inv);
        o[2] = make_float4(f[8] * inv,  f[9] * inv,  f[10] * inv, f[11] * inv);
        o[3] = make_float4(f[12] * inv, f[13] * inv, f[14] * inv, f[15] * inv);
    }
}

// ---------------------------------------------------------------------------
extern "C" void kernel_launch(void* const* d_in, const int* in_sizes, int n_in,
                              void* d_out, int out_size) {
    const float* Zs = (const float*)d_in[0];
    const int*   Ys = (const int*)d_in[1];
    const float* Zq = (const float*)d_in[2];
    const float* log_ls = (const float*)d_in[3];
    const float* log_noise = (const float*)d_in[4];
    (void)n_in; (void)out_size; (void)in_sizes;

    convert_kernel<<<NS / 8, 256>>>(Zs, NS, 0);
    convert_kernel<<<QN / 8, 256>>>(Zq, QN, 1);
    kss_kernel<<<dim3(NS / 16, NS / 16), dim3(16, 16)>>>(Zs, log_ls, log_noise);

    cudaFuncSetAttribute(chol_panel_kernel,
                         cudaFuncAttributeMaxDynamicSharedMemorySize, NS * 65 * 4);
    for (int p = 0; p < NS / 64; ++p) {
        int rows = NS - p * 64;
        chol_panel_kernel<<<1, 1024, rows * 65 * sizeof(float)>>>(p);
        int j1 = p * 64 + 64;
        if (j1 < NS) {
            int m = NS - j1;
            syrk_kernel<<<dim3(m / 16, m / 16), dim3(16, 16)>>>(j1);
        }
    }
    transpose_kernel<<<dim3(NS / 32, NS / 32), dim3(32, 8)>>>();

    cudaFuncSetAttribute(solve2_kernel,
                         cudaFuncAttributeMaxDynamicSharedMemorySize, SOLVE_SMEM);
    solve2_kernel<<<1, 1024, SOLVE_SMEM>>>(Ys);

    cudaFuncSetAttribute(fused_hmma_kernel,
                         cudaFuncAttributeMaxDynamicSharedMemorySize, FUSED_SMEM);
    fused_hmma_kernel<<<QN / 128, 256, FUSED_SMEM>>>(log_ls, (float*)d_out);
}

// round 5
// speedup vs baseline: 3.6610x; 1.3298x over previous
#include <cuda_runtime.h>
#include <cuda_bf16.h>
#include <math.h>
#include <stdint.h>

constexpr int NS = 512;    // support samples
constexpr int D  = 1024;   // feature dim
constexpr int NW = 16;     // classes
constexpr int QN = 65536;  // queries

// ---------------------------------------------------------------------------
// Device-global scratch (no allocations allowed)
// ---------------------------------------------------------------------------
__device__ float g_Kss[NS * NS];
__device__ float g_LT[NS * NS];
__device__ float g_sqs[NS];
__device__ float g_sqq[QN];
__device__ float g_Minv[8 * 64 * 64];
__device__ __align__(16) __nv_bfloat16 g_alpha_bf[NS * NW];
// bf16, K-chunked (64 elems = 128B per row-chunk) + XOR-swizzled 16B chunks
__device__ uint4 g_Zq_r[(size_t)QN * 128];
__device__ uint4 g_Zs_r[(size_t)NS * 128];

// ---------------------------------------------------------------------------
// sm_80-compatible PTX helpers (NO tcgen05 — harness compiles at sm_100)
// ---------------------------------------------------------------------------
__device__ __forceinline__ uint32_t smem_u32(const void* p) {
    uint32_t a;
    asm("{ .reg .u64 t; cvta.to.shared.u64 t, %1; cvt.u32.u64 %0, t; }" : "=r"(a) : "l"(p));
    return a;
}
__device__ __forceinline__ void cp_async16(uint32_t dst, const void* src) {
    asm volatile("cp.async.cg.shared.global [%0], [%1], 16;" :: "r"(dst), "l"(src));
}
__device__ __forceinline__ void ldsm_x4(uint32_t& r0, uint32_t& r1, uint32_t& r2, uint32_t& r3,
                                        uint32_t addr) {
    asm volatile("ldmatrix.sync.aligned.m8n8.x4.shared.b16 {%0,%1,%2,%3}, [%4];"
                 : "=r"(r0), "=r"(r1), "=r"(r2), "=r"(r3) : "r"(addr));
}
__device__ __forceinline__ void ldsm_x4_t(uint32_t& r0, uint32_t& r1, uint32_t& r2, uint32_t& r3,
                                          uint32_t addr) {
    asm volatile("ldmatrix.sync.aligned.m8n8.x4.trans.shared.b16 {%0,%1,%2,%3}, [%4];"
                 : "=r"(r0), "=r"(r1), "=r"(r2), "=r"(r3) : "r"(addr));
}
__device__ __forceinline__ void mma_bf16(float* c, uint32_t a0, uint32_t a1, uint32_t a2,
                                         uint32_t a3, uint32_t b0, uint32_t b1) {
    asm volatile(
        "mma.sync.aligned.m16n8k16.row.col.f32.bf16.bf16.f32 "
        "{%0,%1,%2,%3}, {%4,%5,%6,%7}, {%8,%9}, {%0,%1,%2,%3};"
        : "+f"(c[0]), "+f"(c[1]), "+f"(c[2]), "+f"(c[3])
        : "r"(a0), "r"(a1), "r"(a2), "r"(a3), "r"(b0), "r"(b1));
}
__device__ __forceinline__ uint32_t pack_bf16(float lo, float hi) {
    uint32_t r;
    asm("cvt.rn.bf16x2.f32 %0, %1, %2;" : "=r"(r) : "f"(hi), "f"(lo));
    return r;
}

// ---------------------------------------------------------------------------
// 0) fp32 -> bf16 K-chunked swizzled layout + row sq-norms (warp per row)
// ---------------------------------------------------------------------------
__global__ void convert_kernel(const float* __restrict__ Z, int nrows, int is_q) {
    uint4* outv = is_q ? g_Zq_r : g_Zs_r;
    float* sq   = is_q ? g_sqq  : g_sqs;
    const int row = (blockIdx.x * blockDim.x + threadIdx.x) >> 5;
    const int lane = threadIdx.x & 31;
    if (row >= nrows) return;
    const float4* src = (const float4*)(Z + (size_t)row * D);
    float ss = 0.f;
    #pragma unroll
    for (int it = 0; it < 4; ++it) {
        int m = it * 32 + lane;            // 16B-chunk id 0..127
        int kt = m >> 3, c16 = m & 7;
        float4 a = src[m * 2], b = src[m * 2 + 1];
        ss += a.x*a.x + a.y*a.y + a.z*a.z + a.w*a.w
            + b.x*b.x + b.y*b.y + b.z*b.z + b.w*b.w;
        uint4 o;
        o.x = pack_bf16(a.x, a.y); o.y = pack_bf16(a.z, a.w);
        o.z = pack_bf16(b.x, b.y); o.w = pack_bf16(b.z, b.w);
        outv[((size_t)kt * nrows + row) * 8 + (c16 ^ (row & 7))] = o;
    }
    #pragma unroll
    for (int d = 16; d; d >>= 1) ss += __shfl_xor_sync(0xffffffffu, ss, d);
    if (lane == 0) sq[row] = ss;
}

// ---------------------------------------------------------------------------
// 1) Kss = rbf(Zs,Zs) + noise*I (fp32)
// ---------------------------------------------------------------------------
__global__ void kss_kernel(const float* __restrict__ Zs,
                           const float* __restrict__ log_ls_p,
                           const float* __restrict__ log_noise_p) {
    __shared__ float a[16][17], b[16][17];
    int tx = threadIdx.x, ty = threadIdx.y;
    int row = blockIdx.y * 16 + ty;
    int col = blockIdx.x * 16 + tx;
    float acc = 0.f;
    for (int kt = 0; kt < D; kt += 16) {
        a[ty][tx] = Zs[(size_t)row * D + kt + tx];
        b[ty][tx] = Zs[(size_t)(blockIdx.x * 16 + ty) * D + kt + tx];
        __syncthreads();
        #pragma unroll
        for (int k = 0; k < 16; ++k) acc += a[ty][k] * b[tx][k];
        __syncthreads();
    }
    float inv2  = 0.5f * __expf(-2.0f * (*log_ls_p));
    float noise = __expf(2.0f * (*log_noise_p));
    float d2 = fmaxf(g_sqs[row] + g_sqs[col] - 2.0f * acc, 0.0f);
    g_Kss[row * NS + col] = __expf(-d2 * inv2) + (row == col ? noise : 0.0f);
}

// ---------------------------------------------------------------------------
// 2) Panel factorization: Crout 64x64 diag (1 warp) + explicit inv(L11)
//    (64 half-warp groups) + TRSM as GEMM X = A21 * Minv^T (all threads)
// ---------------------------------------------------------------------------
constexpr int PANEL_SMEM_MAX = (512 * 65 + 64 * 65 + 64) * 4;

__global__ void __launch_bounds__(1024) panel2_kernel(int p) {
    extern __shared__ float S[];
    const int j0 = p * 64;
    const int rows = NS - j0;
    const int rb = rows - 64;
    float* P    = S;                    // [rows][65]
    float* Mi   = S + rows * 65;        // [64][65]
    float* invd = Mi + 64 * 65;         // [64]
    const int tid = threadIdx.x, lane = tid & 31, w = tid >> 5;

    for (int e = tid; e < rows * 64; e += 1024) {
        int r = e >> 6, cc = e & 63;
        P[r * 65 + cc] = g_Kss[(size_t)(j0 + r) * NS + j0 + cc];
    }
    for (int e = tid; e < 64 * 65; e += 1024) Mi[e] = 0.f;
    __syncthreads();

    // --- Crout factor of diag block with warp 0 only (no block barriers) ---
    if (w == 0) {
        for (int j = 0; j < 64; ++j) {
            for (int i = j + lane; i < 64; i += 32) {
                float acc = P[i * 65 + j];
                for (int k = 0; k < j; ++k)
                    acc -= P[i * 65 + k] * P[j * 65 + k];
                P[i * 65 + j] = acc;
            }
            __syncwarp();
            float s = sqrtf(P[j * 65 + j]);
            float inv = 1.0f / s;
            for (int i = j + lane; i < 64; i += 32)
                P[i * 65 + j] = (i == j) ? s : P[i * 65 + j] * inv;
            if (lane == 0) invd[j] = inv;
            __syncwarp();
        }
    }
    __syncthreads();

    // --- Minv = inv(L11): 64 half-warp groups, one unit-column each ---
    {
        const int g = tid >> 4, l = tid & 15;
        for (int j = 0; j < 64; ++j) {
            float s = 0.f;
            for (int k = g + l; k < j; k += 16)
                s += P[j * 65 + k] * Mi[k * 65 + g];
            #pragma unroll
            for (int d = 8; d; d >>= 1) s += __shfl_xor_sync(0xffffffffu, s, d);
            if (l == 0 && j >= g)
                Mi[j * 65 + g] = (((j == g) ? 1.0f : 0.0f) - s) * invd[j];
            __syncwarp();
        }
    }
    __syncthreads();

    // --- store diag block + Minv ---
    for (int e = tid; e < 64 * 64; e += 1024) {
        int r = e >> 6, cc = e & 63;
        g_Kss[(size_t)(j0 + r) * NS + j0 + cc] = P[r * 65 + cc];
        g_Minv[p * 4096 + e] = Mi[r * 65 + cc];
    }

    // --- TRSM as GEMM: L21[r][j] = sum_{k<=j} A21[r][k] * Minv[j][k] ---
    for (int e = tid; e < rb * 64; e += 1024) {
        int r = 64 + (e >> 6), j = e & 63;
        float acc = 0.f;
        for (int k = 0; k <= j; ++k)
            acc += P[r * 65 + k] * Mi[j * 65 + k];
        g_Kss[(size_t)(j0 + r) * NS + j0 + j] = acc;
    }
}

__global__ void syrk_kernel(int j1) {
    __shared__ float Pi[16 * 65], Pk[16 * 65];
    const int j0 = j1 - 64;
    int tx = threadIdx.x, ty = threadIdx.y;
    int tid = ty * 16 + tx;
    int i = j1 + blockIdx.y * 16 + ty;
    int k = j1 + blockIdx.x * 16 + tx;
    for (int e = tid; e < 16 * 64; e += 256) {
        int r = e >> 6, l = e & 63;
        Pi[r * 65 + l] = g_Kss[(size_t)(j1 + blockIdx.y * 16 + r) * NS + j0 + l];
        Pk[r * 65 + l] = g_Kss[(size_t)(j1 + blockIdx.x * 16 + r) * NS + j0 + l];
    }
    __syncthreads();
    float acc = 0.f;
    #pragma unroll
    for (int l = 0; l < 64; ++l) acc += Pi[ty * 65 + l] * Pk[tx * 65 + l];
    g_Kss[(size_t)i * NS + k] -= acc;
}

__global__ void transpose_kernel() {
    __shared__ float t[32][33];
    int x = blockIdx.x * 32 + threadIdx.x;
    int y = blockIdx.y * 32 + threadIdx.y;
    #pragma unroll
    for (int j = 0; j < 32; j += 8)
        t[threadIdx.y + j][threadIdx.x] = g_Kss[(size_t)(y + j) * NS + x];
    __syncthreads();
    x = blockIdx.y * 32 + threadIdx.x;
    y = blockIdx.x * 32 + threadIdx.y;
    #pragma unroll
    for (int j = 0; j < 32; j += 8)
        g_LT[(size_t)(y + j) * NS + x] = t[threadIdx.x][threadIdx.y + j];
}

// ---------------------------------------------------------------------------
// 3) Block-parallel triangular solves via stored Minv blocks (no substitution)
// ---------------------------------------------------------------------------
constexpr int S3_SMEM = (512 * 16 + 64 * 65 + 64 * 16) * 4 + 512 * 4;

__global__ void __launch_bounds__(1024) solve3_kernel(const int* __restrict__ Ys) {
    extern __shared__ float s3[];
    float* ysm = s3;                     // [512][16]
    float* Mi  = s3 + 512 * 16;          // [64][65]
    float* rhs = Mi + 64 * 65;           // [64][16]
    int*   yls = (int*)(rhs + 64 * 16);  // [512]
    const int tid = threadIdx.x;
    const int r = tid >> 4, c = tid & 15;
    for (int i = tid; i < NS; i += 1024) yls[i] = Ys[i];
    __syncthreads();
    // forward: L y = onehot
    for (int bi = 0; bi < 8; ++bi) {
        const int i0 = bi * 64;
        float pacc = 0.f;
        const float* Lr = g_Kss + (size_t)(i0 + r) * NS;
        for (int k = 0; k < i0; ++k) pacc += Lr[k] * ysm[k * 16 + c];
        for (int e = tid; e < 4096; e += 1024)
            Mi[(e >> 6) * 65 + (e & 63)] = g_Minv[bi * 4096 + e];
        rhs[r * 16 + c] = ((yls[i0 + r] == c) ? 1.0f : 0.0f) - pacc;
        __syncthreads();
        float acc = 0.f;
        #pragma unroll 8
        for (int k = 0; k < 64; ++k) acc += Mi[r * 65 + k] * rhs[k * 16 + c];
        ysm[(i0 + r) * 16 + c] = acc;
        __syncthreads();
    }
    // backward: L^T x = y  (x = Minv^T rhs per block)
    for (int bi = 7; bi >= 0; --bi) {
        const int i0 = bi * 64, i1 = i0 + 64;
        float pacc = 0.f;
        const float* Lr = g_LT + (size_t)(i0 + r) * NS;
        for (int k = i1; k < NS; ++k) pacc += Lr[k] * ysm[k * 16 + c];
        for (int e = tid; e < 4096; e += 1024)
            Mi[(e >> 6) * 65 + (e & 63)] = g_Minv[bi * 4096 + e];
        rhs[r * 16 + c] = ysm[(i0 + r) * 16 + c] - pacc;
        __syncthreads();
        float acc = 0.f;
        #pragma unroll 8
        for (int k = 0; k < 64; ++k) acc += Mi[k * 65 + r] * rhs[k * 16 + c];
        ysm[(i0 + r) * 16 + c] = acc;
        __syncthreads();
    }
    for (int e = tid; e < NS * NW; e += 1024)
        g_alpha_bf[e] = __float2bfloat16(ysm[e]);
}

// ---------------------------------------------------------------------------
// 4) fused main kernel: HMMA GEMM (128 x 512 x 1024) -> exp -> HMMA @alpha -> softmax
// ---------------------------------------------------------------------------
constexpr int NST = 4;
constexpr int STG_BYTES = 32768;                 // A 16KB + B 16KB per stage
constexpr int OFF_KV   = NST * STG_BYTES;        // 131072, 32KB kv tile
constexpr int OFF_AL   = OFF_KV + 32768;         // 163840, 512 x 48B alpha
constexpr int OFF_FRED = OFF_AL + 512 * 48;      // 188416, 128 x 17 fp32
constexpr int OFF_SQQ  = OFF_FRED + 128 * 17 * 4;  // 197120
constexpr int OFF_SQS  = OFF_SQQ + 512;          // 197632
constexpr int FUSED_SMEM = OFF_SQS + 2048;       // 199680

__global__ void __launch_bounds__(256, 1)
fused_hmma_kernel(const float* __restrict__ log_ls_p, float* __restrict__ out) {
    extern __shared__ __align__(16) char sm[];
    const uint32_t sb = smem_u32(sm);
    float* sqq  = (float*)(sm + OFF_SQQ);
    float* sqs  = (float*)(sm + OFF_SQS);
    float* fred = (float*)(sm + OFF_FRED);
    const int tid = threadIdx.x, lane = tid & 31, w = tid >> 5;
    const int q0 = blockIdx.x * 128;
    const int wm = w & 3, wn = w >> 2;           // row-block 32, col-block 64
    const int jr = lane & 7, jg = lane >> 3;     // ldmatrix address lane roles
    const float inv2 = 0.5f * __expf(-2.0f * (*log_ls_p));

    for (int i = tid; i < 128; i += 256) sqq[i] = g_sqq[q0 + i];
    for (int i = tid; i < 512; i += 256) sqs[i] = g_sqs[i];
    for (int i = tid; i < 1024; i += 256) {
        int s = i >> 1, h = i & 1;
        *(uint4*)(sm + OFF_AL + s * 48 + h * 16) = ((const uint4*)g_alpha_bf)[i];
    }

    auto issue = [&](int it) {
        int st = it >> 4, kt = it & 15;
        uint32_t buf = sb + (uint32_t)(it & (NST - 1)) * STG_BYTES;
        const char* Ag = (const char*)g_Zq_r + ((size_t)kt * QN + q0) * 128;
        const char* Bg = (const char*)g_Zs_r + ((size_t)kt * NS + st * 128) * 128;
        #pragma unroll
        for (int i = 0; i < 4; ++i) {
            int ch = tid + i * 256;
            cp_async16(buf + ch * 16, Ag + ch * 16);
        }
        #pragma unroll
        for (int i = 0; i < 4; ++i) {
            int ch = tid + i * 256;
            cp_async16(buf + 16384 + ch * 16, Bg + ch * 16);
        }
        asm volatile("cp.async.commit_group;");
    };
    issue(0); issue(1); issue(2);

    float acc[2][8][4];
    float acc2[2][4] = {0.f, 0.f, 0.f, 0.f, 0.f, 0.f, 0.f, 0.f};

    #pragma unroll 1
    for (int it = 0; it < 64; ++it) {
        const int kt = it & 15, st = it >> 4;
        if (kt == 0) {
            #pragma unroll
            for (int rt = 0; rt < 2; ++rt)
                #pragma unroll
                for (int ct = 0; ct < 8; ++ct)
                    #pragma unroll
                    for (int e = 0; e < 4; ++e) acc[rt][ct][e] = 0.f;
        }
        if (it <= 60) asm volatile("cp.async.wait_group 2;");
        else          asm volatile("cp.async.wait_group 0;");
        __syncthreads();

        const uint32_t Ab = sb + (uint32_t)(it & (NST - 1)) * STG_BYTES;
        const uint32_t Bb = Ab + 16384;
        #pragma unroll
        for (int ks = 0; ks < 4; ++ks) {
            uint32_t a[2][4];
            #pragma unroll
            for (int rt = 0; rt < 2; ++rt) {
                int r = wm * 32 + rt * 16 + (jg & 1) * 8 + jr;
                int c = (ks * 2 + (jg >> 1)) ^ jr;
                ldsm_x4(a[rt][0], a[rt][1], a[rt][2], a[rt][3], Ab + (r * 8 + c) * 16);
            }
            #pragma unroll
            for (int nt = 0; nt < 4; ++nt) {
                uint32_t b0, b1, b2, b3;
                int n = wn * 64 + nt * 16 + (jg >> 1) * 8 + jr;
                int c = (ks * 2 + (jg & 1)) ^ jr;
                ldsm_x4(b0, b1, b2, b3, Bb + (n * 8 + c) * 16);
                #pragma unroll
                for (int rt = 0; rt < 2; ++rt) {
                    mma_bf16(acc[rt][nt * 2],     a[rt][0], a[rt][1], a[rt][2], a[rt][3], b0, b1);
                    mma_bf16(acc[rt][nt * 2 + 1], a[rt][0], a[rt][1], a[rt][2], a[rt][3], b2, b3);
                }
            }
        }

        if (kt == 15) {
            #pragma unroll
            for (int rt = 0; rt < 2; ++rt) {
                int ql = wm * 32 + rt * 16 + (lane >> 2);
                float sqlo = sqq[ql], sqhi = sqq[ql + 8];
                #pragma unroll
                for (int ct = 0; ct < 8; ++ct) {
                    int c0 = wn * 64 + ct * 8 + (lane & 3) * 2;
                    float sa = sqs[st * 128 + c0], sc = sqs[st * 128 + c0 + 1];
                    float* cc = acc[rt][ct];
                    float k00 = __expf(-fmaxf(sqlo + sa - 2.f * cc[0], 0.f) * inv2);
                    float k01 = __expf(-fmaxf(sqlo + sc - 2.f * cc[1], 0.f) * inv2);
                    float k10 = __expf(-fmaxf(sqhi + sa - 2.f * cc[2], 0.f) * inv2);
                    float k11 = __expf(-fmaxf(sqhi + sc - 2.f * cc[3], 0.f) * inv2);
                    int chn = wn * 8 + ct, w0 = (lane & 3) * 4;
                    int qh = ql + 8;
                    *(uint32_t*)(sm + OFF_KV + (ql * 16 + (chn ^ (ql & 7))) * 16 + w0) =
                        pack_bf16(k00, k01);
                    *(uint32_t*)(sm + OFF_KV + (qh * 16 + (chn ^ (qh & 7))) * 16 + w0) =
                        pack_bf16(k10, k11);
                }
            }
            __syncthreads();
            #pragma unroll
            for (int k2 = 0; k2 < 8; ++k2) {
                uint32_t a0, a1, a2, a3, b0, b1, b2, b3;
                int r = w * 16 + (jg & 1) * 8 + jr;
                int c = (k2 * 2 + (jg >> 1)) ^ jr;
                ldsm_x4(a0, a1, a2, a3, sb + OFF_KV + (r * 16 + c) * 16);
                int s = st * 128 + k2 * 16 + (jg & 1) * 8 + jr;
                int h = jg >> 1;
                ldsm_x4_t(b0, b1, b2, b3, sb + OFF_AL + s * 48 + h * 16);
                mma_bf16(acc2[0], a0, a1, a2, a3, b0, b1);
                mma_bf16(acc2[1], a0, a1, a2, a3, b2, b3);
            }
            __syncthreads();
        }
        if (it + 3 < 64) issue(it + 3);
    }

    {
        int r = w * 16 + (lane >> 2);
        #pragma unroll
        for (int ct = 0; ct < 2; ++ct) {
            int c0 = ct * 8 + (lane & 3) * 2;
            fred[r * 17 + c0]           = acc2[ct][0];
            fred[r * 17 + c0 + 1]       = acc2[ct][1];
            fred[(r + 8) * 17 + c0]     = acc2[ct][2];
            fred[(r + 8) * 17 + c0 + 1] = acc2[ct][3];
        }
    }
    __syncthreads();
    if (tid < 128) {
        float f[16];
        #pragma unroll
        for (int c = 0; c < 16; ++c) f[c] = fred[tid * 17 + c];
        float mx = f[0];
        #pragma unroll
        for (int c = 1; c < 16; ++c) mx = fmaxf(mx, f[c]);
        float sum = 0.f;
        #pragma unroll
        for (int c = 0; c < 16; ++c) { f[c] = __expf(f[c] - mx); sum += f[c]; }
        float inv = 1.0f / sum;
        float4* o = (float4*)(out + (size_t)(q0 + tid) * 16);
        o[0] = make_float4(f[0] * inv,  f[1] * inv,  f[2] * inv,  f[3] * inv);
        o[1] = make_float4(f[4] * inv,  f[5] * inv,  f[6] * inv,  f[7] * inv);
        o[2] = make_float4(f[8] * inv,  f[9] * inv,  f[10] * inv, f[11] * inv);
        o[3] = make_float4(f[12] * inv, f[13] * inv, f[14] * inv, f[15] * inv);
    }
}

// ---------------------------------------------------------------------------
extern "C" void kernel_launch(void* const* d_in, const int* in_sizes, int n_in,
                              void* d_out, int out_size) {
    const float* Zs = (const float*)d_in[0];
    const int*   Ys = (const int*)d_in[1];
    const float* Zq = (const float*)d_in[2];
    const float* log_ls = (const float*)d_in[3];
    const float* log_noise = (const float*)d_in[4];
    (void)n_in; (void)out_size; (void)in_sizes;

    convert_kernel<<<NS / 8, 256>>>(Zs, NS, 0);
    convert_kernel<<<QN / 8, 256>>>(Zq, QN, 1);
    kss_kernel<<<dim3(NS / 16, NS / 16), dim3(16, 16)>>>(Zs, log_ls, log_noise);

    cudaFuncSetAttribute(panel2_kernel,
                         cudaFuncAttributeMaxDynamicSharedMemorySize, PANEL_SMEM_MAX);
    for (int p = 0; p < NS / 64; ++p) {
        int rows = NS - p * 64;
        panel2_kernel<<<1, 1024, (rows * 65 + 64 * 65 + 64) * 4>>>(p);
        int j1 = p * 64 + 64;
        if (j1 < NS) {
            int m = NS - j1;
            syrk_kernel<<<dim3(m / 16, m / 16), dim3(16, 16)>>>(j1);
        }
    }
    transpose_kernel<<<dim3(NS / 32, NS / 32), dim3(32, 8)>>>();

    cudaFuncSetAttribute(solve3_kernel,
                         cudaFuncAttributeMaxDynamicSharedMemorySize, S3_SMEM);
    solve3_kernel<<<1, 1024, S3_SMEM>>>(Ys);

    cudaFuncSetAttribute(fused_hmma_kernel,
                         cudaFuncAttributeMaxDynamicSharedMemorySize, FUSED_SMEM);
    fused_hmma_kernel<<<QN / 128, 256, FUSED_SMEM>>>(log_ls, (float*)d_out);
}

// round 6
// speedup vs baseline: 3.9164x; 1.0698x over previous
#include <cuda_runtime.h>
#include <cuda_bf16.h>
#include <math.h>
#include <stdint.h>

constexpr int NS = 512;    // support samples
constexpr int D  = 1024;   // feature dim
constexpr int NW = 16;     // classes
constexpr int QN = 65536;  // queries

// ---------------------------------------------------------------------------
// Device-global scratch (no allocations allowed)
// ---------------------------------------------------------------------------
__device__ float g_Kss[NS * NS];
__device__ float g_LT[NS * NS];
__device__ float g_sqs[NS];
__device__ float g_sqq[QN];
__device__ float g_Minv[8 * 64 * 64];
__device__ __align__(16) __nv_bfloat16 g_alpha_bf[NS * NW];
// bf16, K-chunked (64 elems = 128B per row-chunk) + XOR-swizzled 16B chunks
__device__ uint4 g_Zq_r[(size_t)QN * 128];
__device__ uint4 g_Zs_r[(size_t)NS * 128];

// ---------------------------------------------------------------------------
// sm_80-compatible PTX helpers (NO tcgen05 — harness compiles at sm_100)
// ---------------------------------------------------------------------------
__device__ __forceinline__ uint32_t smem_u32(const void* p) {
    uint32_t a;
    asm("{ .reg .u64 t; cvta.to.shared.u64 t, %1; cvt.u32.u64 %0, t; }" : "=r"(a) : "l"(p));
    return a;
}
__device__ __forceinline__ void cp_async16(uint32_t dst, const void* src) {
    asm volatile("cp.async.cg.shared.global [%0], [%1], 16;" :: "r"(dst), "l"(src));
}
__device__ __forceinline__ void ldsm_x4(uint32_t& r0, uint32_t& r1, uint32_t& r2, uint32_t& r3,
                                        uint32_t addr) {
    asm volatile("ldmatrix.sync.aligned.m8n8.x4.shared.b16 {%0,%1,%2,%3}, [%4];"
                 : "=r"(r0), "=r"(r1), "=r"(r2), "=r"(r3) : "r"(addr));
}
__device__ __forceinline__ void ldsm_x4_t(uint32_t& r0, uint32_t& r1, uint32_t& r2, uint32_t& r3,
                                          uint32_t addr) {
    asm volatile("ldmatrix.sync.aligned.m8n8.x4.trans.shared.b16 {%0,%1,%2,%3}, [%4];"
                 : "=r"(r0), "=r"(r1), "=r"(r2), "=r"(r3) : "r"(addr));
}
__device__ __forceinline__ void mma_bf16(float* c, uint32_t a0, uint32_t a1, uint32_t a2,
                                         uint32_t a3, uint32_t b0, uint32_t b1) {
    asm volatile(
        "mma.sync.aligned.m16n8k16.row.col.f32.bf16.bf16.f32 "
        "{%0,%1,%2,%3}, {%4,%5,%6,%7}, {%8,%9}, {%0,%1,%2,%3};"
        : "+f"(c[0]), "+f"(c[1]), "+f"(c[2]), "+f"(c[3])
        : "r"(a0), "r"(a1), "r"(a2), "r"(a3), "r"(b0), "r"(b1));
}
__device__ __forceinline__ uint32_t pack_bf16(float lo, float hi) {
    uint32_t r;
    asm("cvt.rn.bf16x2.f32 %0, %1, %2;" : "=r"(r) : "f"(hi), "f"(lo));
    return r;
}

// ---------------------------------------------------------------------------
// 0) fp32 -> bf16 K-chunked swizzled layout + row sq-norms (warp per row)
// ---------------------------------------------------------------------------
__global__ void convert_kernel(const float* __restrict__ Z, int nrows, int is_q) {
    uint4* outv = is_q ? g_Zq_r : g_Zs_r;
    float* sq   = is_q ? g_sqq  : g_sqs;
    const int row = (blockIdx.x * blockDim.x + threadIdx.x) >> 5;
    const int lane = threadIdx.x & 31;
    if (row >= nrows) return;
    const float4* src = (const float4*)(Z + (size_t)row * D);
    float ss = 0.f;
    #pragma unroll
    for (int it = 0; it < 4; ++it) {
        int m = it * 32 + lane;            // 16B-chunk id 0..127
        int kt = m >> 3, c16 = m & 7;
        float4 a = src[m * 2], b = src[m * 2 + 1];
        ss += a.x*a.x + a.y*a.y + a.z*a.z + a.w*a.w
            + b.x*b.x + b.y*b.y + b.z*b.z + b.w*b.w;
        uint4 o;
        o.x = pack_bf16(a.x, a.y); o.y = pack_bf16(a.z, a.w);
        o.z = pack_bf16(b.x, b.y); o.w = pack_bf16(b.z, b.w);
        outv[((size_t)kt * nrows + row) * 8 + (c16 ^ (row & 7))] = o;
    }
    #pragma unroll
    for (int d = 16; d; d >>= 1) ss += __shfl_xor_sync(0xffffffffu, ss, d);
    if (lane == 0) sq[row] = ss;
}

// ---------------------------------------------------------------------------
// 1) Kss = rbf(Zs,Zs) + noise*I (fp32)
// ---------------------------------------------------------------------------
__global__ void kss_kernel(const float* __restrict__ Zs,
                           const float* __restrict__ log_ls_p,
                           const float* __restrict__ log_noise_p) {
    __shared__ float a[16][17], b[16][17];
    int tx = threadIdx.x, ty = threadIdx.y;
    int row = blockIdx.y * 16 + ty;
    int col = blockIdx.x * 16 + tx;
    float acc = 0.f;
    for (int kt = 0; kt < D; kt += 16) {
        a[ty][tx] = Zs[(size_t)row * D + kt + tx];
        b[ty][tx] = Zs[(size_t)(blockIdx.x * 16 + ty) * D + kt + tx];
        __syncthreads();
        #pragma unroll
        for (int k = 0; k < 16; ++k) acc += a[ty][k] * b[tx][k];
        __syncthreads();
    }
    float inv2  = 0.5f * __expf(-2.0f * (*log_ls_p));
    float noise = __expf(2.0f * (*log_noise_p));
    float d2 = fmaxf(g_sqs[row] + g_sqs[col] - 2.0f * acc, 0.0f);
    g_Kss[row * NS + col] = __expf(-d2 * inv2) + (row == col ? noise : 0.0f);
}

// ---------------------------------------------------------------------------
// 2a) Diag-block factorization (64x64, block-parallel right-looking) + Minv
// ---------------------------------------------------------------------------
__global__ void __launch_bounds__(256) panel_diag_kernel(int p) {
    __shared__ float P[64 * 65];
    __shared__ float Mi[64 * 65];
    __shared__ float invd[64];
    const int j0 = p * 64;
    const int tid = threadIdx.x;

    for (int e = tid; e < 64 * 64; e += 256) {
        int r = e >> 6, c = e & 63;
        P[r * 65 + c] = g_Kss[(size_t)(j0 + r) * NS + j0 + c];
    }
    for (int e = tid; e < 64 * 65; e += 256) Mi[e] = 0.f;
    __syncthreads();

    // right-looking Cholesky on the 64x64 block; trailing update block-parallel
    for (int j = 0; j < 64; ++j) {
        if (tid == 0) {
            float s = sqrtf(P[j * 65 + j]);
            P[j * 65 + j] = s;
            invd[j] = 1.0f / s;
        }
        __syncthreads();
        if (tid > j && tid < 64) P[tid * 65 + j] *= invd[j];
        __syncthreads();
        {
            int c = tid & 63;
            if (c > j) {
                float pc = P[c * 65 + j];
                #pragma unroll 4
                for (int i = j + 1 + (tid >> 6); i < 64; i += 4)
                    if (c <= i) P[i * 65 + c] -= P[i * 65 + j] * pc;
            }
        }
        __syncthreads();
    }

    // Minv = inv(L): 64 quad-lane groups, one unit column each
    {
        const int g = tid >> 2, l = tid & 3;
        for (int j = 0; j < 64; ++j) {
            float s = 0.f;
            for (int k = g + l; k < j; k += 4)
                s += P[j * 65 + k] * Mi[k * 65 + g];
            s += __shfl_xor_sync(0xffffffffu, s, 1);
            s += __shfl_xor_sync(0xffffffffu, s, 2);
            if (l == 0 && j >= g)
                Mi[j * 65 + g] = (((j == g) ? 1.0f : 0.0f) - s) * invd[j];
            __syncwarp();
        }
    }
    __syncthreads();

    for (int e = tid; e < 64 * 64; e += 256) {
        int r = e >> 6, c = e & 63;
        g_Kss[(size_t)(j0 + r) * NS + j0 + c] = P[r * 65 + c];
        g_Minv[p * 4096 + e] = Mi[r * 65 + c];
    }
}

// ---------------------------------------------------------------------------
// 2b) Panel TRSM as grid GEMM: L21 = A21 * Minv^T  (64 rows per block)
// ---------------------------------------------------------------------------
__global__ void __launch_bounds__(256) trsm_kernel(int p) {
    __shared__ float As[64 * 65];
    __shared__ float Mi[64 * 65];
    const int j0 = p * 64;
    const int r0 = j0 + 64 + blockIdx.x * 64;
    const int tid = threadIdx.x;
    for (int e = tid; e < 64 * 64; e += 256) {
        int r = e >> 6, c = e & 63;
        As[r * 65 + c] = g_Kss[(size_t)(r0 + r) * NS + j0 + c];
        Mi[r * 65 + c] = g_Minv[p * 4096 + e];
    }
    __syncthreads();
    const int r = tid >> 2, l = tid & 3;
    float o[16];
    #pragma unroll
    for (int jj = 0; jj < 16; ++jj) {
        int j = jj * 4 + l;
        float acc = 0.f;
        for (int k = 0; k <= j; ++k)
            acc += As[r * 65 + k] * Mi[j * 65 + k];
        o[jj] = acc;
    }
    #pragma unroll
    for (int jj = 0; jj < 16; ++jj)
        g_Kss[(size_t)(r0 + r) * NS + j0 + jj * 4 + l] = o[jj];
}

// ---------------------------------------------------------------------------
// 2c) trailing SYRK update (lower triangle only)
// ---------------------------------------------------------------------------
__global__ void syrk_kernel(int j1) {
    if (blockIdx.x > blockIdx.y) return;   // upper triangle never read
    __shared__ float Pi[16 * 65], Pk[16 * 65];
    const int j0 = j1 - 64;
    int tx = threadIdx.x, ty = threadIdx.y;
    int tid = ty * 16 + tx;
    int i = j1 + blockIdx.y * 16 + ty;
    int k = j1 + blockIdx.x * 16 + tx;
    for (int e = tid; e < 16 * 64; e += 256) {
        int r = e >> 6, l = e & 63;
        Pi[r * 65 + l] = g_Kss[(size_t)(j1 + blockIdx.y * 16 + r) * NS + j0 + l];
        Pk[r * 65 + l] = g_Kss[(size_t)(j1 + blockIdx.x * 16 + r) * NS + j0 + l];
    }
    __syncthreads();
    float acc = 0.f;
    #pragma unroll
    for (int l = 0; l < 64; ++l) acc += Pi[ty * 65 + l] * Pk[tx * 65 + l];
    g_Kss[(size_t)i * NS + k] -= acc;
}

__global__ void transpose_kernel() {
    __shared__ float t[32][33];
    int x = blockIdx.x * 32 + threadIdx.x;
    int y = blockIdx.y * 32 + threadIdx.y;
    #pragma unroll
    for (int j = 0; j < 32; j += 8)
        t[threadIdx.y + j][threadIdx.x] = g_Kss[(size_t)(y + j) * NS + x];
    __syncthreads();
    x = blockIdx.y * 32 + threadIdx.x;
    y = blockIdx.x * 32 + threadIdx.y;
    #pragma unroll
    for (int j = 0; j < 32; j += 8)
        g_LT[(size_t)(y + j) * NS + x] = t[threadIdx.x][threadIdx.y + j];
}

// ---------------------------------------------------------------------------
// 3) Block-parallel triangular solves via stored Minv blocks (no substitution)
// ---------------------------------------------------------------------------
constexpr int S3_SMEM = (512 * 16 + 64 * 65 + 64 * 16) * 4 + 512 * 4;

__global__ void __launch_bounds__(1024) solve3_kernel(const int* __restrict__ Ys) {
    extern __shared__ float s3[];
    float* ysm = s3;                     // [512][16]
    float* Mi  = s3 + 512 * 16;          // [64][65]
    float* rhs = Mi + 64 * 65;           // [64][16]
    int*   yls = (int*)(rhs + 64 * 16);  // [512]
    const int tid = threadIdx.x;
    const int r = tid >> 4, c = tid & 15;
    for (int i = tid; i < NS; i += 1024) yls[i] = Ys[i];
    __syncthreads();
    // forward: L y = onehot
    for (int bi = 0; bi < 8; ++bi) {
        const int i0 = bi * 64;
        float pacc = 0.f;
        const float* Lr = g_Kss + (size_t)(i0 + r) * NS;
        for (int k = 0; k < i0; ++k) pacc += Lr[k] * ysm[k * 16 + c];
        for (int e = tid; e < 4096; e += 1024)
            Mi[(e >> 6) * 65 + (e & 63)] = g_Minv[bi * 4096 + e];
        rhs[r * 16 + c] = ((yls[i0 + r] == c) ? 1.0f : 0.0f) - pacc;
        __syncthreads();
        float acc = 0.f;
        #pragma unroll 8
        for (int k = 0; k < 64; ++k) acc += Mi[r * 65 + k] * rhs[k * 16 + c];
        ysm[(i0 + r) * 16 + c] = acc;
        __syncthreads();
    }
    // backward: L^T x = y  (x = Minv^T rhs per block)
    for (int bi = 7; bi >= 0; --bi) {
        const int i0 = bi * 64, i1 = i0 + 64;
        float pacc = 0.f;
        const float* Lr = g_LT + (size_t)(i0 + r) * NS;
        for (int k = i1; k < NS; ++k) pacc += Lr[k] * ysm[k * 16 + c];
        for (int e = tid; e < 4096; e += 1024)
            Mi[(e >> 6) * 65 + (e & 63)] = g_Minv[bi * 4096 + e];
        rhs[r * 16 + c] = ysm[(i0 + r) * 16 + c] - pacc;
        __syncthreads();
        float acc = 0.f;
        #pragma unroll 8
        for (int k = 0; k < 64; ++k) acc += Mi[k * 65 + r] * rhs[k * 16 + c];
        ysm[(i0 + r) * 16 + c] = acc;
        __syncthreads();
    }
    for (int e = tid; e < NS * NW; e += 1024)
        g_alpha_bf[e] = __float2bfloat16(ysm[e]);
}

// ---------------------------------------------------------------------------
// 4) fused main kernel: HMMA GEMM (128 x 512 x 1024) -> exp -> HMMA @alpha -> softmax
// ---------------------------------------------------------------------------
constexpr int NST = 4;
constexpr int STG_BYTES = 32768;                 // A 16KB + B 16KB per stage
constexpr int OFF_KV   = NST * STG_BYTES;        // 131072, 32KB kv tile
constexpr int OFF_AL   = OFF_KV + 32768;         // 163840, 512 x 48B alpha
constexpr int OFF_FRED = OFF_AL + 512 * 48;      // 188416, 128 x 17 fp32
constexpr int OFF_SQQ  = OFF_FRED + 128 * 17 * 4;  // 197120
constexpr int OFF_SQS  = OFF_SQQ + 512;          // 197632
constexpr int FUSED_SMEM = OFF_SQS + 2048;       // 199680

__global__ void __launch_bounds__(256, 1)
fused_hmma_kernel(const float* __restrict__ log_ls_p, float* __restrict__ out) {
    extern __shared__ __align__(16) char sm[];
    const uint32_t sb = smem_u32(sm);
    float* sqq  = (float*)(sm + OFF_SQQ);
    float* sqs  = (float*)(sm + OFF_SQS);
    float* fred = (float*)(sm + OFF_FRED);
    const int tid = threadIdx.x, lane = tid & 31, w = tid >> 5;
    const int q0 = blockIdx.x * 128;
    const int wm = w & 3, wn = w >> 2;           // row-block 32, col-block 64
    const int jr = lane & 7, jg = lane >> 3;     // ldmatrix address lane roles
    const float inv2 = 0.5f * __expf(-2.0f * (*log_ls_p));

    for (int i = tid; i < 128; i += 256) sqq[i] = g_sqq[q0 + i];
    for (int i = tid; i < 512; i += 256) sqs[i] = g_sqs[i];
    for (int i = tid; i < 1024; i += 256) {
        int s = i >> 1, h = i & 1;
        *(uint4*)(sm + OFF_AL + s * 48 + h * 16) = ((const uint4*)g_alpha_bf)[i];
    }

    auto issue = [&](int it) {
        int st = it >> 4, kt = it & 15;
        uint32_t buf = sb + (uint32_t)(it & (NST - 1)) * STG_BYTES;
        const char* Ag = (const char*)g_Zq_r + ((size_t)kt * QN + q0) * 128;
        const char* Bg = (const char*)g_Zs_r + ((size_t)kt * NS + st * 128) * 128;
        #pragma unroll
        for (int i = 0; i < 4; ++i) {
            int ch = tid + i * 256;
            cp_async16(buf + ch * 16, Ag + ch * 16);
        }
        #pragma unroll
        for (int i = 0; i < 4; ++i) {
            int ch = tid + i * 256;
            cp_async16(buf + 16384 + ch * 16, Bg + ch * 16);
        }
        asm volatile("cp.async.commit_group;");
    };
    issue(0); issue(1); issue(2);

    float acc[2][8][4];
    float acc2[2][4] = {0.f, 0.f, 0.f, 0.f, 0.f, 0.f, 0.f, 0.f};

    #pragma unroll 1
    for (int it = 0; it < 64; ++it) {
        const int kt = it & 15, st = it >> 4;
        if (kt == 0) {
            #pragma unroll
            for (int rt = 0; rt < 2; ++rt)
                #pragma unroll
                for (int ct = 0; ct < 8; ++ct)
                    #pragma unroll
                    for (int e = 0; e < 4; ++e) acc[rt][ct][e] = 0.f;
        }
        if (it <= 60) asm volatile("cp.async.wait_group 2;");
        else          asm volatile("cp.async.wait_group 0;");
        __syncthreads();

        const uint32_t Ab = sb + (uint32_t)(it & (NST - 1)) * STG_BYTES;
        const uint32_t Bb = Ab + 16384;
        #pragma unroll
        for (int ks = 0; ks < 4; ++ks) {
            uint32_t a[2][4];
            #pragma unroll
            for (int rt = 0; rt < 2; ++rt) {
                int r = wm * 32 + rt * 16 + (jg & 1) * 8 + jr;
                int c = (ks * 2 + (jg >> 1)) ^ jr;
                ldsm_x4(a[rt][0], a[rt][1], a[rt][2], a[rt][3], Ab + (r * 8 + c) * 16);
            }
            #pragma unroll
            for (int nt = 0; nt < 4; ++nt) {
                uint32_t b0, b1, b2, b3;
                int n = wn * 64 + nt * 16 + (jg >> 1) * 8 + jr;
                int c = (ks * 2 + (jg & 1)) ^ jr;
                ldsm_x4(b0, b1, b2, b3, Bb + (n * 8 + c) * 16);
                #pragma unroll
                for (int rt = 0; rt < 2; ++rt) {
                    mma_bf16(acc[rt][nt * 2],     a[rt][0], a[rt][1], a[rt][2], a[rt][3], b0, b1);
                    mma_bf16(acc[rt][nt * 2 + 1], a[rt][0], a[rt][1], a[rt][2], a[rt][3], b2, b3);
                }
            }
        }

        if (kt == 15) {
            #pragma unroll
            for (int rt = 0; rt < 2; ++rt) {
                int ql = wm * 32 + rt * 16 + (lane >> 2);
                float sqlo = sqq[ql], sqhi = sqq[ql + 8];
                #pragma unroll
                for (int ct = 0; ct < 8; ++ct) {
                    int c0 = wn * 64 + ct * 8 + (lane & 3) * 2;
                    float sa = sqs[st * 128 + c0], sc = sqs[st * 128 + c0 + 1];
                    float* cc = acc[rt][ct];
                    float k00 = __expf(-fmaxf(sqlo + sa - 2.f * cc[0], 0.f) * inv2);
                    float k01 = __expf(-fmaxf(sqlo + sc - 2.f * cc[1], 0.f) * inv2);
                    float k10 = __expf(-fmaxf(sqhi + sa - 2.f * cc[2], 0.f) * inv2);
                    float k11 = __expf(-fmaxf(sqhi + sc - 2.f * cc[3], 0.f) * inv2);
                    int chn = wn * 8 + ct, w0 = (lane & 3) * 4;
                    int qh = ql + 8;
                    *(uint32_t*)(sm + OFF_KV + (ql * 16 + (chn ^ (ql & 7))) * 16 + w0) =
                        pack_bf16(k00, k01);
                    *(uint32_t*)(sm + OFF_KV + (qh * 16 + (chn ^ (qh & 7))) * 16 + w0) =
                        pack_bf16(k10, k11);
                }
            }
            __syncthreads();
            #pragma unroll
            for (int k2 = 0; k2 < 8; ++k2) {
                uint32_t a0, a1, a2, a3, b0, b1, b2, b3;
                int r = w * 16 + (jg & 1) * 8 + jr;
                int c = (k2 * 2 + (jg >> 1)) ^ jr;
                ldsm_x4(a0, a1, a2, a3, sb + OFF_KV + (r * 16 + c) * 16);
                int s = st * 128 + k2 * 16 + (jg & 1) * 8 + jr;
                int h = jg >> 1;
                ldsm_x4_t(b0, b1, b2, b3, sb + OFF_AL + s * 48 + h * 16);
                mma_bf16(acc2[0], a0, a1, a2, a3, b0, b1);
                mma_bf16(acc2[1], a0, a1, a2, a3, b2, b3);
            }
            __syncthreads();
        }
        if (it + 3 < 64) issue(it + 3);
    }

    {
        int r = w * 16 + (lane >> 2);
        #pragma unroll
        for (int ct = 0; ct < 2; ++ct) {
            int c0 = ct * 8 + (lane & 3) * 2;
            fred[r * 17 + c0]           = acc2[ct][0];
            fred[r * 17 + c0 + 1]       = acc2[ct][1];
            fred[(r + 8) * 17 + c0]     = acc2[ct][2];
            fred[(r + 8) * 17 + c0 + 1] = acc2[ct][3];
        }
    }
    __syncthreads();
    if (tid < 128) {
        float f[16];
        #pragma unroll
        for (int c = 0; c < 16; ++c) f[c] = fred[tid * 17 + c];
        float mx = f[0];
        #pragma unroll
        for (int c = 1; c < 16; ++c) mx = fmaxf(mx, f[c]);
        float sum = 0.f;
        #pragma unroll
        for (int c = 0; c < 16; ++c) { f[c] = __expf(f[c] - mx); sum += f[c]; }
        float inv = 1.0f / sum;
        float4* o = (float4*)(out + (size_t)(q0 + tid) * 16);
        o[0] = make_float4(f[0] * inv,  f[1] * inv,  f[2] * inv,  f[3] * inv);
        o[1] = make_float4(f[4] * inv,  f[5] * inv,  f[6] * inv,  f[7] * inv);
        o[2] = make_float4(f[8] * inv,  f[9] * inv,  f[10] * inv, f[11] * inv);
        o[3] = make_float4(f[12] * inv, f[13] * inv, f[14] * inv, f[15] * inv);
    }
}

// ---------------------------------------------------------------------------
extern "C" void kernel_launch(void* const* d_in, const int* in_sizes, int n_in,
                              void* d_out, int out_size) {
    const float* Zs = (const float*)d_in[0];
    const int*   Ys = (const int*)d_in[1];
    const float* Zq = (const float*)d_in[2];
    const float* log_ls = (const float*)d_in[3];
    const float* log_noise = (const float*)d_in[4];
    (void)n_in; (void)out_size; (void)in_sizes;

    convert_kernel<<<NS / 8, 256>>>(Zs, NS, 0);
    convert_kernel<<<QN / 8, 256>>>(Zq, QN, 1);
    kss_kernel<<<dim3(NS / 16, NS / 16), dim3(16, 16)>>>(Zs, log_ls, log_noise);

    for (int p = 0; p < NS / 64; ++p) {
        panel_diag_kernel<<<1, 256>>>(p);
        int rb = NS - p * 64 - 64;
        if (rb > 0) {
            trsm_kernel<<<rb / 64, 256>>>(p);
            syrk_kernel<<<dim3(rb / 16, rb / 16), dim3(16, 16)>>>(p * 64 + 64);
        }
    }
    transpose_kernel<<<dim3(NS / 32, NS / 32), dim3(32, 8)>>>();

    cudaFuncSetAttribute(solve3_kernel,
                         cudaFuncAttributeMaxDynamicSharedMemorySize, S3_SMEM);
    solve3_kernel<<<1, 1024, S3_SMEM>>>(Ys);

    cudaFuncSetAttribute(fused_hmma_kernel,
                         cudaFuncAttributeMaxDynamicSharedMemorySize, FUSED_SMEM);
    fused_hmma_kernel<<<QN / 128, 256, FUSED_SMEM>>>(log_ls, (float*)d_out);
}

// round 7
// speedup vs baseline: 4.3051x; 1.0992x over previous
#include <cuda_runtime.h>
#include <cuda_bf16.h>
#include <math.h>
#include <stdint.h>

constexpr int NS = 512;    // support samples
constexpr int D  = 1024;   // feature dim
constexpr int NW = 16;     // classes
constexpr int QN = 65536;  // queries

// ---------------------------------------------------------------------------
// Device-global scratch (no allocations allowed)
// ---------------------------------------------------------------------------
__device__ float g_Kss[NS * NS];
__device__ float g_LT[NS * NS];
__device__ float g_sqs[NS];
__device__ float g_sqq[QN];
__device__ float g_Minv[8 * 64 * 64];
__device__ __align__(16) __nv_bfloat16 g_alpha_bf[NS * NW];
// bf16, K-chunked (64 elems = 128B per row-chunk) + XOR-swizzled 16B chunks
__device__ uint4 g_Zq_r[(size_t)QN * 128];
__device__ uint4 g_Zs_r[(size_t)NS * 128];

// ---------------------------------------------------------------------------
// sm_80-compatible PTX helpers (NO tcgen05 — harness compiles at sm_100)
// ---------------------------------------------------------------------------
__device__ __forceinline__ uint32_t smem_u32(const void* p) {
    uint32_t a;
    asm("{ .reg .u64 t; cvta.to.shared.u64 t, %1; cvt.u32.u64 %0, t; }" : "=r"(a) : "l"(p));
    return a;
}
__device__ __forceinline__ void cp_async16(uint32_t dst, const void* src) {
    asm volatile("cp.async.cg.shared.global [%0], [%1], 16;" :: "r"(dst), "l"(src));
}
__device__ __forceinline__ void ldsm_x4(uint32_t& r0, uint32_t& r1, uint32_t& r2, uint32_t& r3,
                                        uint32_t addr) {
    asm volatile("ldmatrix.sync.aligned.m8n8.x4.shared.b16 {%0,%1,%2,%3}, [%4];"
                 : "=r"(r0), "=r"(r1), "=r"(r2), "=r"(r3) : "r"(addr));
}
__device__ __forceinline__ void ldsm_x4_t(uint32_t& r0, uint32_t& r1, uint32_t& r2, uint32_t& r3,
                                          uint32_t addr) {
    asm volatile("ldmatrix.sync.aligned.m8n8.x4.trans.shared.b16 {%0,%1,%2,%3}, [%4];"
                 : "=r"(r0), "=r"(r1), "=r"(r2), "=r"(r3) : "r"(addr));
}
__device__ __forceinline__ void mma_bf16(float* c, uint32_t a0, uint32_t a1, uint32_t a2,
                                         uint32_t a3, uint32_t b0, uint32_t b1) {
    asm volatile(
        "mma.sync.aligned.m16n8k16.row.col.f32.bf16.bf16.f32 "
        "{%0,%1,%2,%3}, {%4,%5,%6,%7}, {%8,%9}, {%0,%1,%2,%3};"
        : "+f"(c[0]), "+f"(c[1]), "+f"(c[2]), "+f"(c[3])
        : "r"(a0), "r"(a1), "r"(a2), "r"(a3), "r"(b0), "r"(b1));
}
__device__ __forceinline__ uint32_t pack_bf16(float lo, float hi) {
    uint32_t r;
    asm("cvt.rn.bf16x2.f32 %0, %1, %2;" : "=r"(r) : "f"(hi), "f"(lo));
    return r;
}

// ---------------------------------------------------------------------------
// 0) fp32 -> bf16 K-chunked swizzled layout + row sq-norms (warp per row)
// ---------------------------------------------------------------------------
__global__ void convert_kernel(const float* __restrict__ Z, int nrows, int is_q) {
    uint4* outv = is_q ? g_Zq_r : g_Zs_r;
    float* sq   = is_q ? g_sqq  : g_sqs;
    const int row = (blockIdx.x * blockDim.x + threadIdx.x) >> 5;
    const int lane = threadIdx.x & 31;
    if (row >= nrows) return;
    const float4* src = (const float4*)(Z + (size_t)row * D);
    float ss = 0.f;
    #pragma unroll
    for (int it = 0; it < 4; ++it) {
        int m = it * 32 + lane;            // 16B-chunk id 0..127
        int kt = m >> 3, c16 = m & 7;
        float4 a = src[m * 2], b = src[m * 2 + 1];
        ss += a.x*a.x + a.y*a.y + a.z*a.z + a.w*a.w
            + b.x*b.x + b.y*b.y + b.z*b.z + b.w*b.w;
        uint4 o;
        o.x = pack_bf16(a.x, a.y); o.y = pack_bf16(a.z, a.w);
        o.z = pack_bf16(b.x, b.y); o.w = pack_bf16(b.z, b.w);
        outv[((size_t)kt * nrows + row) * 8 + (c16 ^ (row & 7))] = o;
    }
    #pragma unroll
    for (int d = 16; d; d >>= 1) ss += __shfl_xor_sync(0xffffffffu, ss, d);
    if (lane == 0) sq[row] = ss;
}

// ---------------------------------------------------------------------------
// 1) Kss = rbf(Zs,Zs) + noise*I (fp32)
// ---------------------------------------------------------------------------
__global__ void kss_kernel(const float* __restrict__ Zs,
                           const float* __restrict__ log_ls_p,
                           const float* __restrict__ log_noise_p) {
    __shared__ float a[16][17], b[16][17];
    int tx = threadIdx.x, ty = threadIdx.y;
    int row = blockIdx.y * 16 + ty;
    int col = blockIdx.x * 16 + tx;
    float acc = 0.f;
    for (int kt = 0; kt < D; kt += 16) {
        a[ty][tx] = Zs[(size_t)row * D + kt + tx];
        b[ty][tx] = Zs[(size_t)(blockIdx.x * 16 + ty) * D + kt + tx];
        __syncthreads();
        #pragma unroll
        for (int k = 0; k < 16; ++k) acc += a[ty][k] * b[tx][k];
        __syncthreads();
    }
    float inv2  = 0.5f * __expf(-2.0f * (*log_ls_p));
    float noise = __expf(2.0f * (*log_noise_p));
    float d2 = fmaxf(g_sqs[row] + g_sqs[col] - 2.0f * acc, 0.0f);
    g_Kss[row * NS + col] = __expf(-d2 * inv2) + (row == col ? noise : 0.0f);
}

// ---------------------------------------------------------------------------
// 2a) 64x64 diag-block Cholesky ONLY (right-looking, tight barriers)
// ---------------------------------------------------------------------------
__global__ void __launch_bounds__(256) chol_diag_kernel(int p) {
    __shared__ float P[64 * 65];
    const int j0 = p * 64;
    const int tid = threadIdx.x;

    for (int e = tid; e < 4096; e += 256) {
        int r = e >> 6, c = e & 63;
        P[r * 65 + c] = g_Kss[(size_t)(j0 + r) * NS + j0 + c];
    }
    __syncthreads();

    const int uc = tid & 63;          // update column
    const int ur = tid >> 6;          // row offset group (0..3)
    for (int j = 0; j < 64; ++j) {
        float d = P[j * 65 + j];
        float sd = sqrtf(d);
        float inv = 1.0f / sd;
        __syncthreads();              // everyone read d before writes
        if (tid < 64 && tid > j) P[tid * 65 + j] *= inv;
        if (tid == j) P[j * 65 + j] = sd;
        __syncthreads();              // column j final
        if (uc > j) {
            float pc = P[uc * 65 + j];
            for (int i = uc + ur; i < 64; i += 4)
                P[i * 65 + uc] -= P[i * 65 + j] * pc;
        }
        __syncthreads();              // trailing updated
    }

    for (int e = tid; e < 4096; e += 256) {
        int r = e >> 6, c = e & 63;
        g_Kss[(size_t)(j0 + r) * NS + j0 + c] = P[r * 65 + c];
    }
}

// ---------------------------------------------------------------------------
// 2b) Panel TRSM: per-row forward substitution vs L11 (row in registers)
//     L21[r][:] solves L21 * L11^T = A21  -> column-sweep substitution
// ---------------------------------------------------------------------------
__global__ void __launch_bounds__(64) trsm_kernel(int p) {
    __shared__ float L[64 * 65];
    const int j0 = p * 64;
    const int r = j0 + 64 + blockIdx.x * 64 + threadIdx.x;
    const int tid = threadIdx.x;
    for (int e = tid; e < 4096; e += 64)
        L[(e >> 6) * 65 + (e & 63)] = g_Kss[(size_t)(j0 + (e >> 6)) * NS + j0 + (e & 63)];
    __syncthreads();

    float x[64];
    #pragma unroll
    for (int j = 0; j < 64; ++j) x[j] = g_Kss[(size_t)r * NS + j0 + j];
    #pragma unroll
    for (int j = 0; j < 64; ++j) {
        float xj = x[j] / L[j * 65 + j];
        x[j] = xj;
        #pragma unroll
        for (int i = j + 1; i < 64; ++i)
            x[i] -= L[i * 65 + j] * xj;
    }
    #pragma unroll
    for (int j = 0; j < 64; ++j) g_Kss[(size_t)r * NS + j0 + j] = x[j];
}

// ---------------------------------------------------------------------------
// 2c) trailing SYRK update (lower triangle only)
// ---------------------------------------------------------------------------
__global__ void syrk_kernel(int j1) {
    if (blockIdx.x > blockIdx.y) return;   // upper triangle never read
    __shared__ float Pi[16 * 65], Pk[16 * 65];
    const int j0 = j1 - 64;
    int tx = threadIdx.x, ty = threadIdx.y;
    int tid = ty * 16 + tx;
    int i = j1 + blockIdx.y * 16 + ty;
    int k = j1 + blockIdx.x * 16 + tx;
    for (int e = tid; e < 16 * 64; e += 256) {
        int r = e >> 6, l = e & 63;
        Pi[r * 65 + l] = g_Kss[(size_t)(j1 + blockIdx.y * 16 + r) * NS + j0 + l];
        Pk[r * 65 + l] = g_Kss[(size_t)(j1 + blockIdx.x * 16 + r) * NS + j0 + l];
    }
    __syncthreads();
    float acc = 0.f;
    #pragma unroll
    for (int l = 0; l < 64; ++l) acc += Pi[ty * 65 + l] * Pk[tx * 65 + l];
    g_Kss[(size_t)i * NS + k] -= acc;
}

// ---------------------------------------------------------------------------
// 2d) All 8 inv(L11) blocks in ONE launch (off the critical panel path)
//     thread g computes column g of inv(L) by column-sweep substitution
// ---------------------------------------------------------------------------
__global__ void __launch_bounds__(64) minv8_kernel() {
    __shared__ float L[64 * 65];
    const int p = blockIdx.x;
    const int j0 = p * 64;
    const int g = threadIdx.x;
    for (int e = g; e < 4096; e += 64)
        L[(e >> 6) * 65 + (e & 63)] = g_Kss[(size_t)(j0 + (e >> 6)) * NS + j0 + (e & 63)];
    __syncthreads();

    float x[64];
    #pragma unroll
    for (int i = 0; i < 64; ++i) x[i] = (i == g) ? 1.0f : 0.0f;
    #pragma unroll
    for (int j = 0; j < 64; ++j) {
        float xj = x[j] / L[j * 65 + j];
        x[j] = xj;
        #pragma unroll
        for (int i = j + 1; i < 64; ++i)
            x[i] -= L[i * 65 + j] * xj;
    }
    #pragma unroll
    for (int j = 0; j < 64; ++j)
        g_Minv[p * 4096 + j * 64 + g] = x[j];   // row-major [j][g], coalesced over g
}

__global__ void transpose_kernel() {
    __shared__ float t[32][33];
    int x = blockIdx.x * 32 + threadIdx.x;
    int y = blockIdx.y * 32 + threadIdx.y;
    #pragma unroll
    for (int j = 0; j < 32; j += 8)
        t[threadIdx.y + j][threadIdx.x] = g_Kss[(size_t)(y + j) * NS + x];
    __syncthreads();
    x = blockIdx.y * 32 + threadIdx.x;
    y = blockIdx.x * 32 + threadIdx.y;
    #pragma unroll
    for (int j = 0; j < 32; j += 8)
        g_LT[(size_t)(y + j) * NS + x] = t[threadIdx.x][threadIdx.y + j];
}

// ---------------------------------------------------------------------------
// 3) Block-parallel triangular solves via stored Minv blocks (no substitution)
// ---------------------------------------------------------------------------
constexpr int S3_SMEM = (512 * 16 + 64 * 65 + 64 * 16) * 4 + 512 * 4;

__global__ void __launch_bounds__(1024) solve3_kernel(const int* __restrict__ Ys) {
    extern __shared__ float s3[];
    float* ysm = s3;                     // [512][16]
    float* Mi  = s3 + 512 * 16;          // [64][65]
    float* rhs = Mi + 64 * 65;           // [64][16]
    int*   yls = (int*)(rhs + 64 * 16);  // [512]
    const int tid = threadIdx.x;
    const int r = tid >> 4, c = tid & 15;
    for (int i = tid; i < NS; i += 1024) yls[i] = Ys[i];
    __syncthreads();
    // forward: L y = onehot
    for (int bi = 0; bi < 8; ++bi) {
        const int i0 = bi * 64;
        float pacc = 0.f;
        const float* Lr = g_Kss + (size_t)(i0 + r) * NS;
        for (int k = 0; k < i0; ++k) pacc += Lr[k] * ysm[k * 16 + c];
        for (int e = tid; e < 4096; e += 1024)
            Mi[(e >> 6) * 65 + (e & 63)] = g_Minv[bi * 4096 + e];
        rhs[r * 16 + c] = ((yls[i0 + r] == c) ? 1.0f : 0.0f) - pacc;
        __syncthreads();
        float acc = 0.f;
        #pragma unroll 8
        for (int k = 0; k < 64; ++k) acc += Mi[r * 65 + k] * rhs[k * 16 + c];
        ysm[(i0 + r) * 16 + c] = acc;
        __syncthreads();
    }
    // backward: L^T x = y  (x = Minv^T rhs per block)
    for (int bi = 7; bi >= 0; --bi) {
        const int i0 = bi * 64, i1 = i0 + 64;
        float pacc = 0.f;
        const float* Lr = g_LT + (size_t)(i0 + r) * NS;
        for (int k = i1; k < NS; ++k) pacc += Lr[k] * ysm[k * 16 + c];
        for (int e = tid; e < 4096; e += 1024)
            Mi[(e >> 6) * 65 + (e & 63)] = g_Minv[bi * 4096 + e];
        rhs[r * 16 + c] = ysm[(i0 + r) * 16 + c] - pacc;
        __syncthreads();
        float acc = 0.f;
        #pragma unroll 8
        for (int k = 0; k < 64; ++k) acc += Mi[k * 65 + r] * rhs[k * 16 + c];
        ysm[(i0 + r) * 16 + c] = acc;
        __syncthreads();
    }
    for (int e = tid; e < NS * NW; e += 1024)
        g_alpha_bf[e] = __float2bfloat16(ysm[e]);
}

// ---------------------------------------------------------------------------
// 4) fused main kernel: HMMA GEMM (128 x 512 x 1024) -> exp -> HMMA @alpha -> softmax
// ---------------------------------------------------------------------------
constexpr int NST = 4;
constexpr int STG_BYTES = 32768;                 // A 16KB + B 16KB per stage
constexpr int OFF_KV   = NST * STG_BYTES;        // 131072, 32KB kv tile
constexpr int OFF_AL   = OFF_KV + 32768;         // 163840, 512 x 48B alpha
constexpr int OFF_FRED = OFF_AL + 512 * 48;      // 188416, 128 x 17 fp32
constexpr int OFF_SQQ  = OFF_FRED + 128 * 17 * 4;  // 197120
constexpr int OFF_SQS  = OFF_SQQ + 512;          // 197632
constexpr int FUSED_SMEM = OFF_SQS + 2048;       // 199680

__global__ void __launch_bounds__(256, 1)
fused_hmma_kernel(const float* __restrict__ log_ls_p, float* __restrict__ out) {
    extern __shared__ __align__(16) char sm[];
    const uint32_t sb = smem_u32(sm);
    float* sqq  = (float*)(sm + OFF_SQQ);
    float* sqs  = (float*)(sm + OFF_SQS);
    float* fred = (float*)(sm + OFF_FRED);
    const int tid = threadIdx.x, lane = tid & 31, w = tid >> 5;
    const int q0 = blockIdx.x * 128;
    const int wm = w & 3, wn = w >> 2;           // row-block 32, col-block 64
    const int jr = lane & 7, jg = lane >> 3;     // ldmatrix address lane roles
    const float inv2 = 0.5f * __expf(-2.0f * (*log_ls_p));

    for (int i = tid; i < 128; i += 256) sqq[i] = g_sqq[q0 + i];
    for (int i = tid; i < 512; i += 256) sqs[i] = g_sqs[i];
    for (int i = tid; i < 1024; i += 256) {
        int s = i >> 1, h = i & 1;
        *(uint4*)(sm + OFF_AL + s * 48 + h * 16) = ((const uint4*)g_alpha_bf)[i];
    }

    auto issue = [&](int it) {
        int st = it >> 4, kt = it & 15;
        uint32_t buf = sb + (uint32_t)(it & (NST - 1)) * STG_BYTES;
        const char* Ag = (const char*)g_Zq_r + ((size_t)kt * QN + q0) * 128;
        const char* Bg = (const char*)g_Zs_r + ((size_t)kt * NS + st * 128) * 128;
        #pragma unroll
        for (int i = 0; i < 4; ++i) {
            int ch = tid + i * 256;
            cp_async16(buf + ch * 16, Ag + ch * 16);
        }
        #pragma unroll
        for (int i = 0; i < 4; ++i) {
            int ch = tid + i * 256;
            cp_async16(buf + 16384 + ch * 16, Bg + ch * 16);
        }
        asm volatile("cp.async.commit_group;");
    };
    issue(0); issue(1); issue(2);

    float acc[2][8][4];
    float acc2[2][4] = {0.f, 0.f, 0.f, 0.f, 0.f, 0.f, 0.f, 0.f};

    #pragma unroll 1
    for (int it = 0; it < 64; ++it) {
        const int kt = it & 15, st = it >> 4;
        if (kt == 0) {
            #pragma unroll
            for (int rt = 0; rt < 2; ++rt)
                #pragma unroll
                for (int ct = 0; ct < 8; ++ct)
                    #pragma unroll
                    for (int e = 0; e < 4; ++e) acc[rt][ct][e] = 0.f;
        }
        if (it <= 60) asm volatile("cp.async.wait_group 2;");
        else          asm volatile("cp.async.wait_group 0;");
        __syncthreads();

        const uint32_t Ab = sb + (uint32_t)(it & (NST - 1)) * STG_BYTES;
        const uint32_t Bb = Ab + 16384;
        #pragma unroll
        for (int ks = 0; ks < 4; ++ks) {
            uint32_t a[2][4];
            #pragma unroll
            for (int rt = 0; rt < 2; ++rt) {
                int r = wm * 32 + rt * 16 + (jg & 1) * 8 + jr;
                int c = (ks * 2 + (jg >> 1)) ^ jr;
                ldsm_x4(a[rt][0], a[rt][1], a[rt][2], a[rt][3], Ab + (r * 8 + c) * 16);
            }
            #pragma unroll
            for (int nt = 0; nt < 4; ++nt) {
                uint32_t b0, b1, b2, b3;
                int n = wn * 64 + nt * 16 + (jg >> 1) * 8 + jr;
                int c = (ks * 2 + (jg & 1)) ^ jr;
                ldsm_x4(b0, b1, b2, b3, Bb + (n * 8 + c) * 16);
                #pragma unroll
                for (int rt = 0; rt < 2; ++rt) {
                    mma_bf16(acc[rt][nt * 2],     a[rt][0], a[rt][1], a[rt][2], a[rt][3], b0, b1);
                    mma_bf16(acc[rt][nt * 2 + 1], a[rt][0], a[rt][1], a[rt][2], a[rt][3], b2, b3);
                }
            }
        }

        if (kt == 15) {
            #pragma unroll
            for (int rt = 0; rt < 2; ++rt) {
                int ql = wm * 32 + rt * 16 + (lane >> 2);
                float sqlo = sqq[ql], sqhi = sqq[ql + 8];
                #pragma unroll
                for (int ct = 0; ct < 8; ++ct) {
                    int c0 = wn * 64 + ct * 8 + (lane & 3) * 2;
                    float sa = sqs[st * 128 + c0], sc = sqs[st * 128 + c0 + 1];
                    float* cc = acc[rt][ct];
                    float k00 = __expf(-fmaxf(sqlo + sa - 2.f * cc[0], 0.f) * inv2);
                    float k01 = __expf(-fmaxf(sqlo + sc - 2.f * cc[1], 0.f) * inv2);
                    float k10 = __expf(-fmaxf(sqhi + sa - 2.f * cc[2], 0.f) * inv2);
                    float k11 = __expf(-fmaxf(sqhi + sc - 2.f * cc[3], 0.f) * inv2);
                    int chn = wn * 8 + ct, w0 = (lane & 3) * 4;
                    int qh = ql + 8;
                    *(uint32_t*)(sm + OFF_KV + (ql * 16 + (chn ^ (ql & 7))) * 16 + w0) =
                        pack_bf16(k00, k01);
                    *(uint32_t*)(sm + OFF_KV + (qh * 16 + (chn ^ (qh & 7))) * 16 + w0) =
                        pack_bf16(k10, k11);
                }
            }
            __syncthreads();
            #pragma unroll
            for (int k2 = 0; k2 < 8; ++k2) {
                uint32_t a0, a1, a2, a3, b0, b1, b2, b3;
                int r = w * 16 + (jg & 1) * 8 + jr;
                int c = (k2 * 2 + (jg >> 1)) ^ jr;
                ldsm_x4(a0, a1, a2, a3, sb + OFF_KV + (r * 16 + c) * 16);
                int s = st * 128 + k2 * 16 + (jg & 1) * 8 + jr;
                int h = jg >> 1;
                ldsm_x4_t(b0, b1, b2, b3, sb + OFF_AL + s * 48 + h * 16);
                mma_bf16(acc2[0], a0, a1, a2, a3, b0, b1);
                mma_bf16(acc2[1], a0, a1, a2, a3, b2, b3);
            }
            __syncthreads();
        }
        if (it + 3 < 64) issue(it + 3);
    }

    {
        int r = w * 16 + (lane >> 2);
        #pragma unroll
        for (int ct = 0; ct < 2; ++ct) {
            int c0 = ct * 8 + (lane & 3) * 2;
            fred[r * 17 + c0]           = acc2[ct][0];
            fred[r * 17 + c0 + 1]       = acc2[ct][1];
            fred[(r + 8) * 17 + c0]     = acc2[ct][2];
            fred[(r + 8) * 17 + c0 + 1] = acc2[ct][3];
        }
    }
    __syncthreads();
    if (tid < 128) {
        float f[16];
        #pragma unroll
        for (int c = 0; c < 16; ++c) f[c] = fred[tid * 17 + c];
        float mx = f[0];
        #pragma unroll
        for (int c = 1; c < 16; ++c) mx = fmaxf(mx, f[c]);
        float sum = 0.f;
        #pragma unroll
        for (int c = 0; c < 16; ++c) { f[c] = __expf(f[c] - mx); sum += f[c]; }
        float inv = 1.0f / sum;
        float4* o = (float4*)(out + (size_t)(q0 + tid) * 16);
        o[0] = make_float4(f[0] * inv,  f[1] * inv,  f[2] * inv,  f[3] * inv);
        o[1] = make_float4(f[4] * inv,  f[5] * inv,  f[6] * inv,  f[7] * inv);
        o[2] = make_float4(f[8] * inv,  f[9] * inv,  f[10] * inv, f[11] * inv);
        o[3] = make_float4(f[12] * inv, f[13] * inv, f[14] * inv, f[15] * inv);
    }
}

// ---------------------------------------------------------------------------
extern "C" void kernel_launch(void* const* d_in, const int* in_sizes, int n_in,
                              void* d_out, int out_size) {
    const float* Zs = (const float*)d_in[0];
    const int*   Ys = (const int*)d_in[1];
    const float* Zq = (const float*)d_in[2];
    const float* log_ls = (const float*)d_in[3];
    const float* log_noise = (const float*)d_in[4];
    (void)n_in; (void)out_size; (void)in_sizes;

    convert_kernel<<<NS / 8, 256>>>(Zs, NS, 0);
    convert_kernel<<<QN / 8, 256>>>(Zq, QN, 1);
    kss_kernel<<<dim3(NS / 16, NS / 16), dim3(16, 16)>>>(Zs, log_ls, log_noise);

    for (int p = 0; p < NS / 64; ++p) {
        chol_diag_kernel<<<1, 256>>>(p);
        int rb = NS - p * 64 - 64;
        if (rb > 0) {
            trsm_kernel<<<rb / 64, 64>>>(p);
            syrk_kernel<<<dim3(rb / 16, rb / 16), dim3(16, 16)>>>(p * 64 + 64);
        }
    }
    minv8_kernel<<<8, 64>>>();
    transpose_kernel<<<dim3(NS / 32, NS / 32), dim3(32, 8)>>>();

    cudaFuncSetAttribute(solve3_kernel,
                         cudaFuncAttributeMaxDynamicSharedMemorySize, S3_SMEM);
    solve3_kernel<<<1, 1024, S3_SMEM>>>(Ys);

    cudaFuncSetAttribute(fused_hmma_kernel,
                         cudaFuncAttributeMaxDynamicSharedMemorySize, FUSED_SMEM);
    fused_hmma_kernel<<<QN / 128, 256, FUSED_SMEM>>>(log_ls, (float*)d_out);
}